// round 1
// baseline (speedup 1.0000x reference)
#include <cuda_runtime.h>
#include <math.h>

typedef unsigned long long u64;

#define NQ    16384
#define NSUP  1024
#define NTOT  17408
#define KTOT  2816
#define HID   128

// scratch (static __device__ — no allocations allowed)
__device__ float g_C [NTOT * HID];   // post-projection features, queries then supports
__device__ float g_qn[NQ   * HID];   // normalized query features
__device__ float g_pn[NSUP * HID];   // normalized support features

// ---- packed f32x2 helpers (Blackwell FFMA2 path) ----
__device__ __forceinline__ u64 fpack(float x, float y) {
    u64 r; asm("mov.b64 %0, {%1, %2};" : "=l"(r) : "f"(x), "f"(y)); return r;
}
__device__ __forceinline__ u64 ffma2(u64 a, u64 b, u64 c) {
    u64 d; asm("fma.rn.f32x2 %0, %1, %2, %3;" : "=l"(d) : "l"(a), "l"(b), "l"(c)); return d;
}
__device__ __forceinline__ float2 funpack(u64 v) {
    float2 f; asm("mov.b64 {%0, %1}, %2;" : "=f"(f.x), "=f"(f.y) : "l"(v)); return f;
}

// =====================================================================
// Kernel 1: fused projection GEMM for ALL tokens (query + support)
//   C[t,n] = sum_k X[t,k] * W[n,k] + bi[n] + bt[n]
//   X = concat(img[2048], txt[768]) per token; W = concat(Wi, Wt) along k
// =====================================================================
#define BM 64
#define BK 16

__global__ __launch_bounds__(256) void proj_kernel(
    const float* __restrict__ qimg, const float* __restrict__ qtxt,
    const float* __restrict__ simg, const float* __restrict__ stxt,
    const float* __restrict__ Wi,   const float* __restrict__ Wt,
    const float* __restrict__ bi,   const float* __restrict__ bt)
{
    __shared__ float As[BK][BM + 4];   // padded: conflict-free staging
    __shared__ float Bs[BK][HID];

    const int tid = threadIdx.x;
    const int t0  = blockIdx.x * BM;

    // A loader: token = t0 + tid/4, 4 consecutive k per thread
    const int a_tok = tid >> 2;
    const int a_k4  = (tid & 3) << 2;
    const float* aimg; const float* atxt;
    {
        int tok = t0 + a_tok;
        if (tok < NQ) { aimg = qimg + (size_t)tok * 2048; atxt = qtxt + (size_t)tok * 768; }
        else { int s = tok - NQ; aimg = simg + (size_t)s * 2048; atxt = stxt + (size_t)s * 768; }
    }
    // B loader: n = tid/2, 8 consecutive k per thread
    const int b_n  = tid >> 1;
    const int b_k8 = (tid & 1) << 3;
    const float* wi_row = Wi + (size_t)b_n * 2048;
    const float* wt_row = Wt + (size_t)b_n * 768;

    // compute mapping: 4 rows, 8 cols split {c0..c0+3, c0+64..c0+67}
    const int rowg = (tid >> 4) << 2;
    const int c0   = (tid & 15) << 2;

    u64 acc[4][4];
    #pragma unroll
    for (int i = 0; i < 4; i++)
        #pragma unroll
        for (int j = 0; j < 4; j++) acc[i][j] = 0ull;

    // prefetch tile 0 (k0 = 0 < 2048 always: img / Wi side)
    float4 a_pf  = *(const float4*)(aimg + a_k4);
    float4 b_pf0 = *(const float4*)(wi_row + b_k8);
    float4 b_pf1 = *(const float4*)(wi_row + b_k8 + 4);

    for (int k0 = 0; k0 < KTOT; k0 += BK) {
        // stage prefetched tile
        As[a_k4+0][a_tok] = a_pf.x; As[a_k4+1][a_tok] = a_pf.y;
        As[a_k4+2][a_tok] = a_pf.z; As[a_k4+3][a_tok] = a_pf.w;
        Bs[b_k8+0][b_n] = b_pf0.x; Bs[b_k8+1][b_n] = b_pf0.y;
        Bs[b_k8+2][b_n] = b_pf0.z; Bs[b_k8+3][b_n] = b_pf0.w;
        Bs[b_k8+4][b_n] = b_pf1.x; Bs[b_k8+5][b_n] = b_pf1.y;
        Bs[b_k8+6][b_n] = b_pf1.z; Bs[b_k8+7][b_n] = b_pf1.w;
        __syncthreads();

        // prefetch next tile (overlap with compute)
        int kn = k0 + BK;
        if (kn < KTOT) {
            int ka = kn + a_k4;
            const float* pa = (ka < 2048) ? (aimg + ka) : (atxt + (ka - 2048));
            a_pf = *(const float4*)pa;
            int kb = kn + b_k8;
            const float* pb = (kb < 2048) ? (wi_row + kb) : (wt_row + (kb - 2048));
            b_pf0 = *(const float4*)pb;
            b_pf1 = *(const float4*)(pb + 4);
        }

        #pragma unroll
        for (int kk = 0; kk < BK; kk++) {
            float4 av = *(const float4*)&As[kk][rowg];
            u64 ad[4];
            ad[0] = fpack(av.x, av.x); ad[1] = fpack(av.y, av.y);
            ad[2] = fpack(av.z, av.z); ad[3] = fpack(av.w, av.w);
            const u64* bp0 = (const u64*)&Bs[kk][c0];
            const u64* bp1 = (const u64*)&Bs[kk][c0 + 64];
            u64 bd[4]; bd[0] = bp0[0]; bd[1] = bp0[1]; bd[2] = bp1[0]; bd[3] = bp1[1];
            #pragma unroll
            for (int i = 0; i < 4; i++)
                #pragma unroll
                for (int j = 0; j < 4; j++)
                    acc[i][j] = ffma2(ad[i], bd[j], acc[i][j]);
        }
        __syncthreads();
    }

    // epilogue: + bi + bt, write C
    int cols[8] = {c0, c0+1, c0+2, c0+3, c0+64, c0+65, c0+66, c0+67};
    #pragma unroll
    for (int i = 0; i < 4; i++) {
        int t = t0 + rowg + i;
        float* out = g_C + (size_t)t * HID;
        #pragma unroll
        for (int j = 0; j < 4; j++) {
            float2 v = funpack(acc[i][j]);
            int ca = cols[j*2], cb = cols[j*2+1];
            out[ca] = v.x + bi[ca] + bt[ca];
            out[cb] = v.y + bi[cb] + bt[cb];
        }
    }
}

// =====================================================================
// shared helpers for the 32-token-per-block pipeline kernel
// =====================================================================
__device__ __forceinline__ void ln32(float (*X)[132], const float* __restrict__ g,
                                     const float* __restrict__ b, int warp, int lane)
{
    float4 gg = *(const float4*)(g + lane*4);
    float4 bb = *(const float4*)(b + lane*4);
    #pragma unroll
    for (int it = 0; it < 4; it++) {
        int t = warp*4 + it;
        float4 v = *(const float4*)&X[t][lane*4];
        float s = v.x + v.y + v.z + v.w;
        #pragma unroll
        for (int o = 16; o; o >>= 1) s += __shfl_xor_sync(0xffffffffu, s, o);
        float mean = s * (1.f/128.f);
        float dx = v.x - mean, dy = v.y - mean, dz = v.z - mean, dw = v.w - mean;
        float sq = dx*dx + dy*dy + dz*dz + dw*dw;
        #pragma unroll
        for (int o = 16; o; o >>= 1) sq += __shfl_xor_sync(0xffffffffu, sq, o);
        float inv = rsqrtf(sq * (1.f/128.f) + 1e-5f);
        v.x = dx*inv*gg.x + bb.x;
        v.y = dy*inv*gg.y + bb.y;
        v.z = dz*inv*gg.z + bb.z;
        v.w = dw*inv*gg.w + bb.w;
        *(float4*)&X[t][lane*4] = v;
    }
}

__device__ __forceinline__ void gemm_tile(const float (*X)[132], float (*Ws)[HID],
                                          const float* __restrict__ W,
                                          float acc[4][4], int tid, int tg, int ng)
{
    const int wn = tid >> 1;
    const int wk = (tid & 1) << 3;
    for (int k0 = 0; k0 < HID; k0 += 16) {
        const float* wr = W + (size_t)wn * HID + k0 + wk;
        float4 w0 = *(const float4*)wr;
        float4 w1 = *(const float4*)(wr + 4);
        Ws[wk+0][wn] = w0.x; Ws[wk+1][wn] = w0.y; Ws[wk+2][wn] = w0.z; Ws[wk+3][wn] = w0.w;
        Ws[wk+4][wn] = w1.x; Ws[wk+5][wn] = w1.y; Ws[wk+6][wn] = w1.z; Ws[wk+7][wn] = w1.w;
        __syncthreads();
        #pragma unroll
        for (int kk = 0; kk < 16; kk++) {
            float4 wv = *(const float4*)&Ws[kk][ng << 2];
            #pragma unroll
            for (int i = 0; i < 4; i++) {
                float x = X[tg*4 + i][k0 + kk];
                acc[i][0] += x * wv.x;
                acc[i][1] += x * wv.y;
                acc[i][2] += x * wv.z;
                acc[i][3] += x * wv.w;
            }
        }
        __syncthreads();
    }
}

// =====================================================================
// Kernel 2: query finish (seq-len-1 attention == v): LN1, Wv, LN2, Wo, L2-norm
// 512 blocks x 256 threads, 32 tokens per block
// =====================================================================
__global__ __launch_bounds__(256) void query_kernel(
    const float* __restrict__ g1, const float* __restrict__ b1,
    const float* __restrict__ Wv, const float* __restrict__ bv,
    const float* __restrict__ g2, const float* __restrict__ b2,
    const float* __restrict__ Wo, const float* __restrict__ bo)
{
    __shared__ float Xs[32][132];
    __shared__ float Ys[32][132];
    __shared__ float Ws[16][HID];
    __shared__ float invn[32];

    const int tid = threadIdx.x;
    const int t0  = blockIdx.x * 32;
    const int warp = tid >> 5, lane = tid & 31;
    const int tg = tid >> 5;       // token group (4 tokens)
    const int ng = tid & 31;       // dim group (4 dims)

    for (int i = tid; i < 1024; i += 256) {
        int r = i >> 5, c4 = (i & 31) << 2;
        *(float4*)&Xs[r][c4] = *(const float4*)(g_C + (size_t)(t0 + r) * HID + c4);
    }
    __syncthreads();
    ln32(Xs, g1, b1, warp, lane);          // LN1 in place
    __syncthreads();

    float accv[4][4] = {};
    gemm_tile(Xs, Ws, Wv, accv, tid, tg, ng);
    #pragma unroll
    for (int i = 0; i < 4; i++)
        #pragma unroll
        for (int j = 0; j < 4; j++)
            Ys[tg*4+i][ng*4+j] = accv[i][j] + bv[ng*4+j];
    __syncthreads();
    ln32(Ys, g2, b2, warp, lane);          // LN2 in place
    __syncthreads();

    float acco[4][4] = {};
    gemm_tile(Ys, Ws, Wo, acco, tid, tg, ng);
    #pragma unroll
    for (int i = 0; i < 4; i++)
        #pragma unroll
        for (int j = 0; j < 4; j++)
            Xs[tg*4+i][ng*4+j] = acco[i][j] + bo[ng*4+j];
    __syncthreads();

    #pragma unroll
    for (int it = 0; it < 4; it++) {
        int t = warp*4 + it;
        float4 v = *(const float4*)&Xs[t][lane*4];
        float sq = v.x*v.x + v.y*v.y + v.z*v.z + v.w*v.w;
        #pragma unroll
        for (int o = 16; o; o >>= 1) sq += __shfl_xor_sync(0xffffffffu, sq, o);
        if (lane == 0) invn[t] = 1.f / fmaxf(sqrtf(sq), 1e-8f);
    }
    __syncthreads();
    #pragma unroll
    for (int i = 0; i < 4; i++) {
        float s = invn[tg*4+i];
        float* out = g_qn + (size_t)(t0 + tg*4 + i) * HID + ng*4;
        #pragma unroll
        for (int j = 0; j < 4; j++) out[j] = Xs[tg*4+i][ng*4+j] * s;
    }
}

// =====================================================================
// Kernel 3: support path — full 4x4 attention per task. 256 blocks x 128 threads
// =====================================================================
__global__ __launch_bounds__(128) void support_kernel(
    const float* __restrict__ g1, const float* __restrict__ b1,
    const float* __restrict__ Wq, const float* __restrict__ bq,
    const float* __restrict__ Wk, const float* __restrict__ bk,
    const float* __restrict__ Wv, const float* __restrict__ bv,
    const float* __restrict__ g2, const float* __restrict__ b2,
    const float* __restrict__ Wo, const float* __restrict__ bo)
{
    __shared__ float Cs[4][HID];
    __shared__ float Ls[4][HID];
    __shared__ float qs[4][HID], ks2[4][HID], vs[4][HID];
    __shared__ float sm[4][4];
    __shared__ float am[4][4];

    const int n = threadIdx.x;          // 0..127 = output dim
    const int task = blockIdx.x;
    const int warp = n >> 5, lane = n & 31;

    #pragma unroll
    for (int i = 0; i < 4; i++)
        Cs[i][n] = g_C[(size_t)(NQ + task*4 + i) * HID + n];
    __syncthreads();

    // LN1: warp w handles token w
    {
        float x0 = Cs[warp][lane], x1 = Cs[warp][lane+32], x2 = Cs[warp][lane+64], x3 = Cs[warp][lane+96];
        float s = x0+x1+x2+x3;
        #pragma unroll
        for (int o = 16; o; o >>= 1) s += __shfl_xor_sync(0xffffffffu, s, o);
        float mean = s * (1.f/128.f);
        float d0=x0-mean, d1=x1-mean, d2=x2-mean, d3=x3-mean;
        float sq = d0*d0 + d1*d1 + d2*d2 + d3*d3;
        #pragma unroll
        for (int o = 16; o; o >>= 1) sq += __shfl_xor_sync(0xffffffffu, sq, o);
        float inv = rsqrtf(sq * (1.f/128.f) + 1e-5f);
        Ls[warp][lane]    = d0*inv*g1[lane]    + b1[lane];
        Ls[warp][lane+32] = d1*inv*g1[lane+32] + b1[lane+32];
        Ls[warp][lane+64] = d2*inv*g1[lane+64] + b1[lane+64];
        Ls[warp][lane+96] = d3*inv*g1[lane+96] + b1[lane+96];
    }
    __syncthreads();

    // q, k, v projections
    {
        float aq[4] = {}, ak[4] = {}, av[4] = {};
        const float* wq = Wq + (size_t)n * HID;
        const float* wk = Wk + (size_t)n * HID;
        const float* wv = Wv + (size_t)n * HID;
        for (int k = 0; k < HID; k++) {
            float q_ = wq[k], k_ = wk[k], v_ = wv[k];
            #pragma unroll
            for (int i = 0; i < 4; i++) {
                float l = Ls[i][k];
                aq[i] += l * q_; ak[i] += l * k_; av[i] += l * v_;
            }
        }
        #pragma unroll
        for (int i = 0; i < 4; i++) {
            qs[i][n]  = aq[i] + bq[n];
            ks2[i][n] = ak[i] + bk[n];
            vs[i][n]  = av[i] + bv[n];
        }
    }
    __syncthreads();

    if (n < 16) {
        int i = n >> 2, j = n & 3;
        float s = 0.f;
        for (int k = 0; k < HID; k++) s += qs[i][k] * ks2[j][k];
        sm[i][j] = s * (1.f / (sqrtf(128.f) + 1e-8f));
    }
    __syncthreads();
    if (n < 4) {
        float r0=sm[n][0], r1=sm[n][1], r2=sm[n][2], r3=sm[n][3];
        float mx = fmaxf(fmaxf(r0, r1), fmaxf(r2, r3));
        float e0=expf(r0-mx), e1=expf(r1-mx), e2=expf(r2-mx), e3=expf(r3-mx);
        float se = e0+e1+e2+e3;
        float a0=e0/se+1e-10f, a1=e1/se+1e-10f, a2=e2/se+1e-10f, a3=e3/se+1e-10f;
        float s2 = a0+a1+a2+a3;
        a0/=s2; a1/=s2; a2/=s2; a3/=s2;
        am[n][0] = fminf(fmaxf(a0, 1e-7f), 1.f);
        am[n][1] = fminf(fmaxf(a1, 1e-7f), 1.f);
        am[n][2] = fminf(fmaxf(a2, 1e-7f), 1.f);
        am[n][3] = fminf(fmaxf(a3, 1e-7f), 1.f);
    }
    __syncthreads();

    // ctx = a @ v  (into Cs)
    #pragma unroll
    for (int i = 0; i < 4; i++)
        Cs[i][n] = am[i][0]*vs[0][n] + am[i][1]*vs[1][n] + am[i][2]*vs[2][n] + am[i][3]*vs[3][n];
    __syncthreads();

    // LN2 into Ls
    {
        float x0 = Cs[warp][lane], x1 = Cs[warp][lane+32], x2 = Cs[warp][lane+64], x3 = Cs[warp][lane+96];
        float s = x0+x1+x2+x3;
        #pragma unroll
        for (int o = 16; o; o >>= 1) s += __shfl_xor_sync(0xffffffffu, s, o);
        float mean = s * (1.f/128.f);
        float d0=x0-mean, d1=x1-mean, d2=x2-mean, d3=x3-mean;
        float sq = d0*d0 + d1*d1 + d2*d2 + d3*d3;
        #pragma unroll
        for (int o = 16; o; o >>= 1) sq += __shfl_xor_sync(0xffffffffu, sq, o);
        float inv = rsqrtf(sq * (1.f/128.f) + 1e-5f);
        Ls[warp][lane]    = d0*inv*g2[lane]    + b2[lane];
        Ls[warp][lane+32] = d1*inv*g2[lane+32] + b2[lane+32];
        Ls[warp][lane+64] = d2*inv*g2[lane+64] + b2[lane+64];
        Ls[warp][lane+96] = d3*inv*g2[lane+96] + b2[lane+96];
    }
    __syncthreads();

    // Wo projection
    {
        float ao[4] = {};
        const float* wo = Wo + (size_t)n * HID;
        for (int k = 0; k < HID; k++) {
            float w = wo[k];
            #pragma unroll
            for (int i = 0; i < 4; i++) ao[i] += Ls[i][k] * w;
        }
        #pragma unroll
        for (int i = 0; i < 4; i++) Cs[i][n] = ao[i] + bo[n];
    }
    __syncthreads();

    // L2-normalize rows, write pn
    {
        float x0 = Cs[warp][lane], x1 = Cs[warp][lane+32], x2 = Cs[warp][lane+64], x3 = Cs[warp][lane+96];
        float sq = x0*x0 + x1*x1 + x2*x2 + x3*x3;
        #pragma unroll
        for (int o = 16; o; o >>= 1) sq += __shfl_xor_sync(0xffffffffu, sq, o);
        float inv = 1.f / fmaxf(sqrtf(sq), 1e-8f);
        float* out = g_pn + (size_t)(task*4 + warp) * HID;
        out[lane]    = x0*inv;
        out[lane+32] = x1*inv;
        out[lane+64] = x2*inv;
        out[lane+96] = x3*inv;
    }
}

// =====================================================================
// Kernel 4: logits[t,q,c] = 10 * qn[t,q,:] . pn[t,c,:]
// 256 blocks x 256 threads (one thread per (q,c))
// =====================================================================
__global__ __launch_bounds__(256) void logits_kernel(float* __restrict__ out)
{
    __shared__ float qns[64][132];
    __shared__ float pns[4][HID];
    const int tid = threadIdx.x;
    const int task = blockIdx.x;

    for (int i = tid; i < 512; i += 256)
        pns[i >> 7][i & 127] = g_pn[(size_t)task*512 + i];
    for (int i = tid; i < 2048; i += 256) {
        int r = i >> 5, c4 = (i & 31) << 2;
        *(float4*)&qns[r][c4] = *(const float4*)(g_qn + (size_t)(task*64 + r)*HID + c4);
    }
    __syncthreads();

    int q = tid >> 2, c = tid & 3;
    float s = 0.f;
    #pragma unroll 8
    for (int k = 0; k < HID; k++) s += qns[q][k] * pns[c][k];
    out[(size_t)task*256 + tid] = s * 10.f;
}

// =====================================================================
extern "C" void kernel_launch(void* const* d_in, const int* in_sizes, int n_in,
                              void* d_out, int out_size)
{
    const float* simg = (const float*)d_in[0];
    const float* stxt = (const float*)d_in[1];
    // d_in[2] = support_labels (int64) — unused by the reference computation
    const float* qimg = (const float*)d_in[3];
    const float* qtxt = (const float*)d_in[4];
    const float* Wi = (const float*)d_in[5];  const float* bi = (const float*)d_in[6];
    const float* Wt = (const float*)d_in[7];  const float* bt = (const float*)d_in[8];
    const float* g1 = (const float*)d_in[9];  const float* b1 = (const float*)d_in[10];
    const float* Wq = (const float*)d_in[11]; const float* bq = (const float*)d_in[12];
    const float* Wk = (const float*)d_in[13]; const float* bk = (const float*)d_in[14];
    const float* Wv = (const float*)d_in[15]; const float* bv = (const float*)d_in[16];
    const float* g2 = (const float*)d_in[17]; const float* b2 = (const float*)d_in[18];
    const float* Wo = (const float*)d_in[19]; const float* bo = (const float*)d_in[20];
    float* out = (float*)d_out;

    proj_kernel<<<NTOT / BM, 256>>>(qimg, qtxt, simg, stxt, Wi, Wt, bi, bt);
    query_kernel<<<512, 256>>>(g1, b1, Wv, bv, g2, b2, Wo, bo);
    support_kernel<<<256, 128>>>(g1, b1, Wq, bq, Wk, bk, Wv, bv, g2, b2, Wo, bo);
    logits_kernel<<<256, 256>>>(out);
}

// round 4
// speedup vs baseline: 1.0983x; 1.0983x over previous
#include <cuda_runtime.h>
#include <math.h>

typedef unsigned long long u64;
typedef unsigned int u32;

#define NQ    16384
#define NSUP  1024
#define NTOT  17408
#define KTOT  2816
#define HID   128

// scratch (static __device__ — no allocations allowed)
__device__ float g_C [NTOT * HID];   // post-projection features, queries then supports
__device__ float g_qn[NQ   * HID];   // normalized query features
__device__ float g_pn[NSUP * HID];   // normalized support features

// =====================================================================
// Kernel 1: tf32 mma.sync projection GEMM
//   C[t,n] = X[t,:]·W[n,:] + bi[n] + bt[n]
//   X = concat(img[2048], txt[768]);  W = concat(Wi, Wt) along k
//   M tile = 128 tokens/CTA (grid 136), N = 128, K chunks of 32.
// =====================================================================
#define BK 32
#define NCH (KTOT / BK)          // 88
#define ROWF 36                  // padded row length in floats (conflict-free)
#define STG_FLOATS (128 * ROWF)  // 4608 floats per matrix per stage
// dynamic smem layout (floats): A0 | B0 | A1 | B1 | bias[128]
#define SMEM_FLOATS (4 * STG_FLOATS + 128)
#define SMEM_BYTES  (SMEM_FLOATS * 4)

// round fp32 bits to nearest tf32 (HW truncates low 13 mantissa bits)
__device__ __forceinline__ u32 rtf(float x) { return __float_as_uint(x) + 0x1000u; }

__device__ __forceinline__ void mma_tf32(float c[4], u32 a0, u32 a1, u32 a2, u32 a3,
                                         u32 b0, u32 b1) {
    asm("mma.sync.aligned.m16n8k8.row.col.f32.tf32.tf32.f32 "
        "{%0,%1,%2,%3}, {%4,%5,%6,%7}, {%8,%9}, {%0,%1,%2,%3};"
        : "+f"(c[0]), "+f"(c[1]), "+f"(c[2]), "+f"(c[3])
        : "r"(a0), "r"(a1), "r"(a2), "r"(a3), "r"(b0), "r"(b1));
}

__global__ __launch_bounds__(256) void proj_mma_kernel(
    const float* __restrict__ qimg, const float* __restrict__ qtxt,
    const float* __restrict__ simg, const float* __restrict__ stxt,
    const float* __restrict__ Wi,   const float* __restrict__ Wt,
    const float* __restrict__ bi,   const float* __restrict__ bt)
{
    extern __shared__ float sm[];
    float* stgA[2] = { sm,                  sm + 2 * STG_FLOATS };
    float* stgB[2] = { sm + STG_FLOATS,     sm + 3 * STG_FLOATS };
    float* bias_s  = sm + 4 * STG_FLOATS;

    const int tid  = threadIdx.x;
    const int lane = tid & 31;

    if (tid < HID) bias_s[tid] = bi[tid] + bt[tid];

    // ---- loader mapping: row = tid/2 (token for A, out-dim for B), 16-float half
    const int lrow = tid >> 1;
    const int h16  = (tid & 1) << 4;
    const float *aimg, *atxt;
    {
        int tok = blockIdx.x * 128 + lrow;
        if (tok < NQ) { aimg = qimg + (size_t)tok * 2048; atxt = qtxt + (size_t)tok * 768; }
        else { int s = tok - NQ; aimg = simg + (size_t)s * 2048; atxt = stxt + (size_t)s * 768; }
    }
    const float* bimg = Wi + (size_t)lrow * 2048;
    const float* btxt = Wt + (size_t)lrow * 768;

    // ---- compute mapping: warp tile 64(M) x 32(N)
    const int w  = tid >> 5;
    const int wm = w & 1;        // 0..1 : M half
    const int wn = w >> 1;       // 0..3 : N quarter
    const int g  = lane >> 2;    // fragment group row
    const int tq = lane & 3;     // fragment col-in-group

    float acc[4][4][4];
    #pragma unroll
    for (int mt = 0; mt < 4; mt++)
        #pragma unroll
        for (int nt = 0; nt < 4; nt++)
            #pragma unroll
            for (int r = 0; r < 4; r++) acc[mt][nt][r] = 0.f;

    // prefetch chunk 0 (img side, k0 = 0)
    float4 ra[4], rb[4];
    #pragma unroll
    for (int i = 0; i < 4; i++) {
        ra[i] = *(const float4*)(aimg + h16 + 4 * i);
        rb[i] = *(const float4*)(bimg + h16 + 4 * i);
    }

    for (int c = 0; c < NCH; c++) {
        const int s = c & 1;
        // stage current chunk (round to tf32 while storing)
        {
            u32* da = (u32*)(stgA[s] + lrow * ROWF + h16);
            u32* db = (u32*)(stgB[s] + lrow * ROWF + h16);
            #pragma unroll
            for (int i = 0; i < 4; i++) {
                uint4 va = { rtf(ra[i].x), rtf(ra[i].y), rtf(ra[i].z), rtf(ra[i].w) };
                uint4 vb = { rtf(rb[i].x), rtf(rb[i].y), rtf(rb[i].z), rtf(rb[i].w) };
                *(uint4*)(da + 4 * i) = va;
                *(uint4*)(db + 4 * i) = vb;
            }
        }
        __syncthreads();

        // prefetch next chunk (LDGs overlap with MMA below)
        if (c + 1 < NCH) {
            int k0 = (c + 1) * BK;
            const float *pa, *pb;
            if (k0 < 2048) { pa = aimg + k0 + h16; pb = bimg + k0 + h16; }
            else           { pa = atxt + (k0 - 2048) + h16; pb = btxt + (k0 - 2048) + h16; }
            #pragma unroll
            for (int i = 0; i < 4; i++) { ra[i] = *(const float4*)(pa + 4 * i); rb[i] = *(const float4*)(pb + 4 * i); }
        }

        // compute on staged chunk: 4 k-steps of 8
        const u32* Au = (const u32*)stgA[s];
        const u32* Bu = (const u32*)stgB[s];
        #pragma unroll
        for (int ks = 0; ks < 4; ks++) {
            const int kc = ks * 8 + tq;
            // b fragments for 4 n-tiles
            u32 bf[4][2];
            #pragma unroll
            for (int nt = 0; nt < 4; nt++) {
                int n = wn * 32 + nt * 8 + g;
                bf[nt][0] = Bu[n * ROWF + kc];
                bf[nt][1] = Bu[n * ROWF + kc + 4];
            }
            #pragma unroll
            for (int mt = 0; mt < 4; mt++) {
                int r = wm * 64 + mt * 16 + g;
                u32 a0 = Au[r * ROWF + kc];
                u32 a1 = Au[(r + 8) * ROWF + kc];
                u32 a2 = Au[r * ROWF + kc + 4];
                u32 a3 = Au[(r + 8) * ROWF + kc + 4];
                #pragma unroll
                for (int nt = 0; nt < 4; nt++)
                    mma_tf32(acc[mt][nt], a0, a1, a2, a3, bf[nt][0], bf[nt][1]);
            }
        }
        __syncthreads();
    }

    // epilogue: + bias, write C
    const int t0 = blockIdx.x * 128;
    #pragma unroll
    for (int mt = 0; mt < 4; mt++) {
        int r0 = t0 + wm * 64 + mt * 16 + g;
        #pragma unroll
        for (int nt = 0; nt < 4; nt++) {
            int cc = wn * 32 + nt * 8 + 2 * tq;
            float bx = bias_s[cc], by = bias_s[cc + 1];
            float2 v0 = { acc[mt][nt][0] + bx, acc[mt][nt][1] + by };
            float2 v1 = { acc[mt][nt][2] + bx, acc[mt][nt][3] + by };
            *(float2*)(g_C + (size_t)r0 * HID + cc)       = v0;
            *(float2*)(g_C + (size_t)(r0 + 8) * HID + cc) = v1;
        }
    }
}

// =====================================================================
// shared helpers for the 32-token-per-block pipeline kernel
// =====================================================================
__device__ __forceinline__ void ln32(float (*X)[132], const float* __restrict__ g,
                                     const float* __restrict__ b, int warp, int lane)
{
    float4 gg = *(const float4*)(g + lane*4);
    float4 bb = *(const float4*)(b + lane*4);
    #pragma unroll
    for (int it = 0; it < 4; it++) {
        int t = warp*4 + it;
        float4 v = *(const float4*)&X[t][lane*4];
        float s = v.x + v.y + v.z + v.w;
        #pragma unroll
        for (int o = 16; o; o >>= 1) s += __shfl_xor_sync(0xffffffffu, s, o);
        float mean = s * (1.f/128.f);
        float dx = v.x - mean, dy = v.y - mean, dz = v.z - mean, dw = v.w - mean;
        float sq = dx*dx + dy*dy + dz*dz + dw*dw;
        #pragma unroll
        for (int o = 16; o; o >>= 1) sq += __shfl_xor_sync(0xffffffffu, sq, o);
        float inv = rsqrtf(sq * (1.f/128.f) + 1e-5f);
        v.x = dx*inv*gg.x + bb.x;
        v.y = dy*inv*gg.y + bb.y;
        v.z = dz*inv*gg.z + bb.z;
        v.w = dw*inv*gg.w + bb.w;
        *(float4*)&X[t][lane*4] = v;
    }
}

__device__ __forceinline__ void gemm_tile(const float (*X)[132], float (*Ws)[HID],
                                          const float* __restrict__ W,
                                          float acc[4][4], int tid, int tg, int ng)
{
    const int wn = tid >> 1;
    const int wk = (tid & 1) << 3;
    for (int k0 = 0; k0 < HID; k0 += 16) {
        const float* wr = W + (size_t)wn * HID + k0 + wk;
        float4 w0 = *(const float4*)wr;
        float4 w1 = *(const float4*)(wr + 4);
        Ws[wk+0][wn] = w0.x; Ws[wk+1][wn] = w0.y; Ws[wk+2][wn] = w0.z; Ws[wk+3][wn] = w0.w;
        Ws[wk+4][wn] = w1.x; Ws[wk+5][wn] = w1.y; Ws[wk+6][wn] = w1.z; Ws[wk+7][wn] = w1.w;
        __syncthreads();
        #pragma unroll
        for (int kk = 0; kk < 16; kk++) {
            float4 wv = *(const float4*)&Ws[kk][ng << 2];
            #pragma unroll
            for (int i = 0; i < 4; i++) {
                float x = X[tg*4 + i][k0 + kk];
                acc[i][0] += x * wv.x;
                acc[i][1] += x * wv.y;
                acc[i][2] += x * wv.z;
                acc[i][3] += x * wv.w;
            }
        }
        __syncthreads();
    }
}

// =====================================================================
// Kernel 2: query finish (seq-len-1 attention == v): LN1, Wv, LN2, Wo, L2-norm
// =====================================================================
__global__ __launch_bounds__(256) void query_kernel(
    const float* __restrict__ g1, const float* __restrict__ b1,
    const float* __restrict__ Wv, const float* __restrict__ bv,
    const float* __restrict__ g2, const float* __restrict__ b2,
    const float* __restrict__ Wo, const float* __restrict__ bo)
{
    __shared__ float Xs[32][132];
    __shared__ float Ys[32][132];
    __shared__ float Ws[16][HID];
    __shared__ float invn[32];

    const int tid = threadIdx.x;
    const int t0  = blockIdx.x * 32;
    const int warp = tid >> 5, lane = tid & 31;
    const int tg = tid >> 5;
    const int ng = tid & 31;

    for (int i = tid; i < 1024; i += 256) {
        int r = i >> 5, c4 = (i & 31) << 2;
        *(float4*)&Xs[r][c4] = *(const float4*)(g_C + (size_t)(t0 + r) * HID + c4);
    }
    __syncthreads();
    ln32(Xs, g1, b1, warp, lane);
    __syncthreads();

    float accv[4][4] = {};
    gemm_tile(Xs, Ws, Wv, accv, tid, tg, ng);
    #pragma unroll
    for (int i = 0; i < 4; i++)
        #pragma unroll
        for (int j = 0; j < 4; j++)
            Ys[tg*4+i][ng*4+j] = accv[i][j] + bv[ng*4+j];
    __syncthreads();
    ln32(Ys, g2, b2, warp, lane);
    __syncthreads();

    float acco[4][4] = {};
    gemm_tile(Ys, Ws, Wo, acco, tid, tg, ng);
    #pragma unroll
    for (int i = 0; i < 4; i++)
        #pragma unroll
        for (int j = 0; j < 4; j++)
            Xs[tg*4+i][ng*4+j] = acco[i][j] + bo[ng*4+j];
    __syncthreads();

    #pragma unroll
    for (int it = 0; it < 4; it++) {
        int t = warp*4 + it;
        float4 v = *(const float4*)&Xs[t][lane*4];
        float sq = v.x*v.x + v.y*v.y + v.z*v.z + v.w*v.w;
        #pragma unroll
        for (int o = 16; o; o >>= 1) sq += __shfl_xor_sync(0xffffffffu, sq, o);
        if (lane == 0) invn[t] = 1.f / fmaxf(sqrtf(sq), 1e-8f);
    }
    __syncthreads();
    #pragma unroll
    for (int i = 0; i < 4; i++) {
        float s = invn[tg*4+i];
        float* out = g_qn + (size_t)(t0 + tg*4 + i) * HID + ng*4;
        #pragma unroll
        for (int j = 0; j < 4; j++) out[j] = Xs[tg*4+i][ng*4+j] * s;
    }
}

// =====================================================================
// Kernel 3: support path — full 4x4 attention per task
// =====================================================================
__global__ __launch_bounds__(128) void support_kernel(
    const float* __restrict__ g1, const float* __restrict__ b1,
    const float* __restrict__ Wq, const float* __restrict__ bq,
    const float* __restrict__ Wk, const float* __restrict__ bk,
    const float* __restrict__ Wv, const float* __restrict__ bv,
    const float* __restrict__ g2, const float* __restrict__ b2,
    const float* __restrict__ Wo, const float* __restrict__ bo)
{
    __shared__ float Cs[4][HID];
    __shared__ float Ls[4][HID];
    __shared__ float qs[4][HID], ks2[4][HID], vs[4][HID];
    __shared__ float sm[4][4];
    __shared__ float am[4][4];

    const int n = threadIdx.x;
    const int task = blockIdx.x;
    const int warp = n >> 5, lane = n & 31;

    #pragma unroll
    for (int i = 0; i < 4; i++)
        Cs[i][n] = g_C[(size_t)(NQ + task*4 + i) * HID + n];
    __syncthreads();

    {
        float x0 = Cs[warp][lane], x1 = Cs[warp][lane+32], x2 = Cs[warp][lane+64], x3 = Cs[warp][lane+96];
        float s = x0+x1+x2+x3;
        #pragma unroll
        for (int o = 16; o; o >>= 1) s += __shfl_xor_sync(0xffffffffu, s, o);
        float mean = s * (1.f/128.f);
        float d0=x0-mean, d1=x1-mean, d2=x2-mean, d3=x3-mean;
        float sq = d0*d0 + d1*d1 + d2*d2 + d3*d3;
        #pragma unroll
        for (int o = 16; o; o >>= 1) sq += __shfl_xor_sync(0xffffffffu, sq, o);
        float inv = rsqrtf(sq * (1.f/128.f) + 1e-5f);
        Ls[warp][lane]    = d0*inv*g1[lane]    + b1[lane];
        Ls[warp][lane+32] = d1*inv*g1[lane+32] + b1[lane+32];
        Ls[warp][lane+64] = d2*inv*g1[lane+64] + b1[lane+64];
        Ls[warp][lane+96] = d3*inv*g1[lane+96] + b1[lane+96];
    }
    __syncthreads();

    {
        float aq[4] = {}, ak[4] = {}, av[4] = {};
        const float* wq = Wq + (size_t)n * HID;
        const float* wk = Wk + (size_t)n * HID;
        const float* wv = Wv + (size_t)n * HID;
        for (int k = 0; k < HID; k++) {
            float q_ = wq[k], k_ = wk[k], v_ = wv[k];
            #pragma unroll
            for (int i = 0; i < 4; i++) {
                float l = Ls[i][k];
                aq[i] += l * q_; ak[i] += l * k_; av[i] += l * v_;
            }
        }
        #pragma unroll
        for (int i = 0; i < 4; i++) {
            qs[i][n]  = aq[i] + bq[n];
            ks2[i][n] = ak[i] + bk[n];
            vs[i][n]  = av[i] + bv[n];
        }
    }
    __syncthreads();

    if (n < 16) {
        int i = n >> 2, j = n & 3;
        float s = 0.f;
        for (int k = 0; k < HID; k++) s += qs[i][k] * ks2[j][k];
        sm[i][j] = s * (1.f / (sqrtf(128.f) + 1e-8f));
    }
    __syncthreads();
    if (n < 4) {
        float r0=sm[n][0], r1=sm[n][1], r2=sm[n][2], r3=sm[n][3];
        float mx = fmaxf(fmaxf(r0, r1), fmaxf(r2, r3));
        float e0=expf(r0-mx), e1=expf(r1-mx), e2=expf(r2-mx), e3=expf(r3-mx);
        float se = e0+e1+e2+e3;
        float a0=e0/se+1e-10f, a1=e1/se+1e-10f, a2=e2/se+1e-10f, a3=e3/se+1e-10f;
        float s2 = a0+a1+a2+a3;
        a0/=s2; a1/=s2; a2/=s2; a3/=s2;
        am[n][0] = fminf(fmaxf(a0, 1e-7f), 1.f);
        am[n][1] = fminf(fmaxf(a1, 1e-7f), 1.f);
        am[n][2] = fminf(fmaxf(a2, 1e-7f), 1.f);
        am[n][3] = fminf(fmaxf(a3, 1e-7f), 1.f);
    }
    __syncthreads();

    #pragma unroll
    for (int i = 0; i < 4; i++)
        Cs[i][n] = am[i][0]*vs[0][n] + am[i][1]*vs[1][n] + am[i][2]*vs[2][n] + am[i][3]*vs[3][n];
    __syncthreads();

    {
        float x0 = Cs[warp][lane], x1 = Cs[warp][lane+32], x2 = Cs[warp][lane+64], x3 = Cs[warp][lane+96];
        float s = x0+x1+x2+x3;
        #pragma unroll
        for (int o = 16; o; o >>= 1) s += __shfl_xor_sync(0xffffffffu, s, o);
        float mean = s * (1.f/128.f);
        float d0=x0-mean, d1=x1-mean, d2=x2-mean, d3=x3-mean;
        float sq = d0*d0 + d1*d1 + d2*d2 + d3*d3;
        #pragma unroll
        for (int o = 16; o; o >>= 1) sq += __shfl_xor_sync(0xffffffffu, sq, o);
        float inv = rsqrtf(sq * (1.f/128.f) + 1e-5f);
        Ls[warp][lane]    = d0*inv*g2[lane]    + b2[lane];
        Ls[warp][lane+32] = d1*inv*g2[lane+32] + b2[lane+32];
        Ls[warp][lane+64] = d2*inv*g2[lane+64] + b2[lane+64];
        Ls[warp][lane+96] = d3*inv*g2[lane+96] + b2[lane+96];
    }
    __syncthreads();

    {
        float ao[4] = {};
        const float* wo = Wo + (size_t)n * HID;
        for (int k = 0; k < HID; k++) {
            float w = wo[k];
            #pragma unroll
            for (int i = 0; i < 4; i++) ao[i] += Ls[i][k] * w;
        }
        #pragma unroll
        for (int i = 0; i < 4; i++) Cs[i][n] = ao[i] + bo[n];
    }
    __syncthreads();

    {
        float x0 = Cs[warp][lane], x1 = Cs[warp][lane+32], x2 = Cs[warp][lane+64], x3 = Cs[warp][lane+96];
        float sq = x0*x0 + x1*x1 + x2*x2 + x3*x3;
        #pragma unroll
        for (int o = 16; o; o >>= 1) sq += __shfl_xor_sync(0xffffffffu, sq, o);
        float inv = 1.f / fmaxf(sqrtf(sq), 1e-8f);
        float* out = g_pn + (size_t)(task*4 + warp) * HID;
        out[lane]    = x0*inv;
        out[lane+32] = x1*inv;
        out[lane+64] = x2*inv;
        out[lane+96] = x3*inv;
    }
}

// =====================================================================
// Kernel 4: logits[t,q,c] = 10 * qn[t,q,:] . pn[t,c,:]
// =====================================================================
__global__ __launch_bounds__(256) void logits_kernel(float* __restrict__ out)
{
    __shared__ float qns[64][132];
    __shared__ float pns[4][HID];
    const int tid = threadIdx.x;
    const int task = blockIdx.x;

    for (int i = tid; i < 512; i += 256)
        pns[i >> 7][i & 127] = g_pn[(size_t)task*512 + i];
    for (int i = tid; i < 2048; i += 256) {
        int r = i >> 5, c4 = (i & 31) << 2;
        *(float4*)&qns[r][c4] = *(const float4*)(g_qn + (size_t)(task*64 + r)*HID + c4);
    }
    __syncthreads();

    int q = tid >> 2, c = tid & 3;
    float s = 0.f;
    #pragma unroll 8
    for (int k = 0; k < HID; k++) s += qns[q][k] * pns[c][k];
    out[(size_t)task*256 + tid] = s * 10.f;
}

// =====================================================================
extern "C" void kernel_launch(void* const* d_in, const int* in_sizes, int n_in,
                              void* d_out, int out_size)
{
    const float* simg = (const float*)d_in[0];
    const float* stxt = (const float*)d_in[1];
    // d_in[2] = support_labels (int64) — unused
    const float* qimg = (const float*)d_in[3];
    const float* qtxt = (const float*)d_in[4];
    const float* Wi = (const float*)d_in[5];  const float* bi = (const float*)d_in[6];
    const float* Wt = (const float*)d_in[7];  const float* bt = (const float*)d_in[8];
    const float* g1 = (const float*)d_in[9];  const float* b1 = (const float*)d_in[10];
    const float* Wq = (const float*)d_in[11]; const float* bq = (const float*)d_in[12];
    const float* Wk = (const float*)d_in[13]; const float* bk = (const float*)d_in[14];
    const float* Wv = (const float*)d_in[15]; const float* bv = (const float*)d_in[16];
    const float* g2 = (const float*)d_in[17]; const float* b2 = (const float*)d_in[18];
    const float* Wo = (const float*)d_in[19]; const float* bo = (const float*)d_in[20];
    float* out = (float*)d_out;

    static int smem_set = 0;
    if (!smem_set) {
        cudaFuncSetAttribute(proj_mma_kernel, cudaFuncAttributeMaxDynamicSharedMemorySize, SMEM_BYTES);
        smem_set = 1;
    }

    proj_mma_kernel<<<NTOT / 128, 256, SMEM_BYTES>>>(qimg, qtxt, simg, stxt, Wi, Wt, bi, bt);
    query_kernel<<<512, 256>>>(g1, b1, Wv, bv, g2, b2, Wo, bo);
    support_kernel<<<256, 128>>>(g1, b1, Wq, bq, Wk, bk, Wv, bv, g2, b2, Wo, bo);
    logits_kernel<<<256, 256>>>(out);
}

// round 6
// speedup vs baseline: 1.1704x; 1.0656x over previous
#include <cuda_runtime.h>
#include <math.h>

typedef unsigned long long u64;
typedef unsigned int u32;

#define NQ    16384
#define NSUP  1024
#define NTOT  17408
#define KTOT  2816
#define HID   128

// scratch (static __device__ — no allocations allowed)
__device__ float g_C [NTOT * HID];   // post-projection features, queries then supports
__device__ float g_qn[NQ   * HID];   // normalized query features
__device__ float g_pn[NSUP * HID];   // normalized support features

// ---- packed f32x2 helpers (Blackwell FFMA2 path) ----
__device__ __forceinline__ u64 fpack(float x, float y) {
    u64 r; asm("mov.b64 %0, {%1, %2};" : "=l"(r) : "f"(x), "f"(y)); return r;
}
__device__ __forceinline__ u64 ffma2(u64 a, u64 b, u64 c) {
    u64 d; asm("fma.rn.f32x2 %0, %1, %2, %3;" : "=l"(d) : "l"(a), "l"(b), "l"(c)); return d;
}
__device__ __forceinline__ float2 funpack(u64 v) {
    float2 f; asm("mov.b64 {%0, %1}, %2;" : "=f"(f.x), "=f"(f.y) : "l"(v)); return f;
}

// =====================================================================
// Kernel 1: FFMA2 projection GEMM v2
//   C[t,n] = X[t,:]·W[n,:] + bi[n] + bt[n]
//   X = concat(img[2048], txt[768]);  W = concat(Wi, Wt) along k
//   Tile 128M x 64N per CTA: grid = 136 M-tiles x 2 N-tiles = 272 CTAs.
//   256 threads, per-thread 8M x 4N, BK = 16, double-buffered smem.
// =====================================================================
#define BKF 16
#define NCHF (KTOT / BKF)   // 176
#define AST 132             // As row stride (floats), 16B-aligned, padded
#define BST 68              // Bs row stride (floats)

__global__ __launch_bounds__(256) void proj_ffma2_kernel(
    const float* __restrict__ qimg, const float* __restrict__ qtxt,
    const float* __restrict__ simg, const float* __restrict__ stxt,
    const float* __restrict__ Wi,   const float* __restrict__ Wt,
    const float* __restrict__ bi,   const float* __restrict__ bt)
{
    __shared__ float As[2][BKF][AST];
    __shared__ float Bs[2][BKF][BST];
    __shared__ float bias_s[64];

    const int tid   = threadIdx.x;
    const int mtile = blockIdx.x >> 1;
    const int n0    = (blockIdx.x & 1) << 6;

    if (tid < 64) bias_s[tid] = bi[n0 + tid] + bt[n0 + tid];

    // ---- A loader: token row = tid/2, k-half = (tid&1)*8
    const int arow = tid >> 1;
    const int akh  = (tid & 1) << 3;
    const float *aimg, *atxt;
    {
        int tok = mtile * 128 + arow;
        if (tok < NQ) { aimg = qimg + (size_t)tok * 2048; atxt = qtxt + (size_t)tok * 768; }
        else { int s = tok - NQ; aimg = simg + (size_t)s * 2048; atxt = stxt + (size_t)s * 768; }
    }
    // ---- B loader: out-dim = n0 + tid/4, 4 k per thread
    const int brow = tid >> 2;
    const int bk4  = (tid & 3) << 2;
    const float* wi_row = Wi + (size_t)(n0 + brow) * 2048;
    const float* wt_row = Wt + (size_t)(n0 + brow) * 768;

    // ---- compute mapping: tm = tid/16 (8-row group), tn = tid%16 (4-col group)
    const int tm = tid >> 4;
    const int tn = tid & 15;

    u64 acc[8][2];
    #pragma unroll
    for (int i = 0; i < 8; i++) { acc[i][0] = 0ull; acc[i][1] = 0ull; }

    // prefetch chunk 0 (k0 = 0: img / Wi side)
    float4 ra0 = *(const float4*)(aimg + akh);
    float4 ra1 = *(const float4*)(aimg + akh + 4);
    float4 rb  = *(const float4*)(wi_row + bk4);

    for (int c = 0; c < NCHF; c++) {
        const int s = c & 1;

        // stage current chunk: A as [k][m], B as [k][n]
        As[s][akh+0][arow] = ra0.x; As[s][akh+1][arow] = ra0.y;
        As[s][akh+2][arow] = ra0.z; As[s][akh+3][arow] = ra0.w;
        As[s][akh+4][arow] = ra1.x; As[s][akh+5][arow] = ra1.y;
        As[s][akh+6][arow] = ra1.z; As[s][akh+7][arow] = ra1.w;
        Bs[s][bk4+0][brow] = rb.x;  Bs[s][bk4+1][brow] = rb.y;
        Bs[s][bk4+2][brow] = rb.z;  Bs[s][bk4+3][brow] = rb.w;
        __syncthreads();

        // prefetch next chunk (overlaps with FFMA2 below)
        if (c + 1 < NCHF) {
            int k0 = (c + 1) * BKF;
            const float *pa, *pb;
            if (k0 < 2048) { pa = aimg + k0 + akh; pb = wi_row + k0 + bk4; }
            else           { pa = atxt + (k0 - 2048) + akh; pb = wt_row + (k0 - 2048) + bk4; }
            ra0 = *(const float4*)pa;
            ra1 = *(const float4*)(pa + 4);
            rb  = *(const float4*)pb;
        }

        // compute 16 k-steps
        #pragma unroll
        for (int kk = 0; kk < BKF; kk++) {
            float4 av0 = *(const float4*)&As[s][kk][tm * 8];
            float4 av1 = *(const float4*)&As[s][kk][tm * 8 + 4];
            const u64* bp = (const u64*)&Bs[s][kk][tn * 4];
            u64 bd0 = bp[0], bd1 = bp[1];
            u64 ad[8];
            ad[0] = fpack(av0.x, av0.x); ad[1] = fpack(av0.y, av0.y);
            ad[2] = fpack(av0.z, av0.z); ad[3] = fpack(av0.w, av0.w);
            ad[4] = fpack(av1.x, av1.x); ad[5] = fpack(av1.y, av1.y);
            ad[6] = fpack(av1.z, av1.z); ad[7] = fpack(av1.w, av1.w);
            #pragma unroll
            for (int i = 0; i < 8; i++) {
                acc[i][0] = ffma2(ad[i], bd0, acc[i][0]);
                acc[i][1] = ffma2(ad[i], bd1, acc[i][1]);
            }
        }
        __syncthreads();
    }

    // epilogue: + bias, vectorized store
    const int t0 = mtile * 128 + tm * 8;
    float4 bb = *(const float4*)&bias_s[tn * 4];
    #pragma unroll
    for (int i = 0; i < 8; i++) {
        float2 v0 = funpack(acc[i][0]);
        float2 v1 = funpack(acc[i][1]);
        float4 o = { v0.x + bb.x, v0.y + bb.y, v1.x + bb.z, v1.y + bb.w };
        *(float4*)(g_C + (size_t)(t0 + i) * HID + n0 + tn * 4) = o;
    }
}

// =====================================================================
// shared helpers for the 32-token-per-block pipeline kernel
// =====================================================================
__device__ __forceinline__ void ln32(float (*X)[132], const float* __restrict__ g,
                                     const float* __restrict__ b, int warp, int lane)
{
    float4 gg = *(const float4*)(g + lane*4);
    float4 bb = *(const float4*)(b + lane*4);
    #pragma unroll
    for (int it = 0; it < 4; it++) {
        int t = warp*4 + it;
        float4 v = *(const float4*)&X[t][lane*4];
        float s = v.x + v.y + v.z + v.w;
        #pragma unroll
        for (int o = 16; o; o >>= 1) s += __shfl_xor_sync(0xffffffffu, s, o);
        float mean = s * (1.f/128.f);
        float dx = v.x - mean, dy = v.y - mean, dz = v.z - mean, dw = v.w - mean;
        float sq = dx*dx + dy*dy + dz*dz + dw*dw;
        #pragma unroll
        for (int o = 16; o; o >>= 1) sq += __shfl_xor_sync(0xffffffffu, sq, o);
        float inv = rsqrtf(sq * (1.f/128.f) + 1e-5f);
        v.x = dx*inv*gg.x + bb.x;
        v.y = dy*inv*gg.y + bb.y;
        v.z = dz*inv*gg.z + bb.z;
        v.w = dw*inv*gg.w + bb.w;
        *(float4*)&X[t][lane*4] = v;
    }
}

__device__ __forceinline__ void gemm_tile(const float (*X)[132], float (*Ws)[HID],
                                          const float* __restrict__ W,
                                          float acc[4][4], int tid, int tg, int ng)
{
    const int wn = tid >> 1;
    const int wk = (tid & 1) << 3;
    for (int k0 = 0; k0 < HID; k0 += 16) {
        const float* wr = W + (size_t)wn * HID + k0 + wk;
        float4 w0 = *(const float4*)wr;
        float4 w1 = *(const float4*)(wr + 4);
        Ws[wk+0][wn] = w0.x; Ws[wk+1][wn] = w0.y; Ws[wk+2][wn] = w0.z; Ws[wk+3][wn] = w0.w;
        Ws[wk+4][wn] = w1.x; Ws[wk+5][wn] = w1.y; Ws[wk+6][wn] = w1.z; Ws[wk+7][wn] = w1.w;
        __syncthreads();
        #pragma unroll
        for (int kk = 0; kk < 16; kk++) {
            float4 wv = *(const float4*)&Ws[kk][ng << 2];
            #pragma unroll
            for (int i = 0; i < 4; i++) {
                float x = X[tg*4 + i][k0 + kk];
                acc[i][0] += x * wv.x;
                acc[i][1] += x * wv.y;
                acc[i][2] += x * wv.z;
                acc[i][3] += x * wv.w;
            }
        }
        __syncthreads();
    }
}

// =====================================================================
// Kernel 2: query finish (seq-len-1 attention == v): LN1, Wv, LN2, Wo, L2-norm
// =====================================================================
__global__ __launch_bounds__(256) void query_kernel(
    const float* __restrict__ g1, const float* __restrict__ b1,
    const float* __restrict__ Wv, const float* __restrict__ bv,
    const float* __restrict__ g2, const float* __restrict__ b2,
    const float* __restrict__ Wo, const float* __restrict__ bo)
{
    __shared__ float Xs[32][132];
    __shared__ float Ys[32][132];
    __shared__ float Ws[16][HID];
    __shared__ float invn[32];

    const int tid = threadIdx.x;
    const int t0  = blockIdx.x * 32;
    const int warp = tid >> 5, lane = tid & 31;
    const int tg = tid >> 5;
    const int ng = tid & 31;

    for (int i = tid; i < 1024; i += 256) {
        int r = i >> 5, c4 = (i & 31) << 2;
        *(float4*)&Xs[r][c4] = *(const float4*)(g_C + (size_t)(t0 + r) * HID + c4);
    }
    __syncthreads();
    ln32(Xs, g1, b1, warp, lane);
    __syncthreads();

    float accv[4][4] = {};
    gemm_tile(Xs, Ws, Wv, accv, tid, tg, ng);
    #pragma unroll
    for (int i = 0; i < 4; i++)
        #pragma unroll
        for (int j = 0; j < 4; j++)
            Ys[tg*4+i][ng*4+j] = accv[i][j] + bv[ng*4+j];
    __syncthreads();
    ln32(Ys, g2, b2, warp, lane);
    __syncthreads();

    float acco[4][4] = {};
    gemm_tile(Ys, Ws, Wo, acco, tid, tg, ng);
    #pragma unroll
    for (int i = 0; i < 4; i++)
        #pragma unroll
        for (int j = 0; j < 4; j++)
            Xs[tg*4+i][ng*4+j] = acco[i][j] + bo[ng*4+j];
    __syncthreads();

    #pragma unroll
    for (int it = 0; it < 4; it++) {
        int t = warp*4 + it;
        float4 v = *(const float4*)&Xs[t][lane*4];
        float sq = v.x*v.x + v.y*v.y + v.z*v.z + v.w*v.w;
        #pragma unroll
        for (int o = 16; o; o >>= 1) sq += __shfl_xor_sync(0xffffffffu, sq, o);
        if (lane == 0) invn[t] = 1.f / fmaxf(sqrtf(sq), 1e-8f);
    }
    __syncthreads();
    #pragma unroll
    for (int i = 0; i < 4; i++) {
        float s = invn[tg*4+i];
        float* out = g_qn + (size_t)(t0 + tg*4 + i) * HID + ng*4;
        #pragma unroll
        for (int j = 0; j < 4; j++) out[j] = Xs[tg*4+i][ng*4+j] * s;
    }
}

// =====================================================================
// Kernel 3: support path — full 4x4 attention per task
// =====================================================================
__global__ __launch_bounds__(128) void support_kernel(
    const float* __restrict__ g1, const float* __restrict__ b1,
    const float* __restrict__ Wq, const float* __restrict__ bq,
    const float* __restrict__ Wk, const float* __restrict__ bk,
    const float* __restrict__ Wv, const float* __restrict__ bv,
    const float* __restrict__ g2, const float* __restrict__ b2,
    const float* __restrict__ Wo, const float* __restrict__ bo)
{
    __shared__ float Cs[4][HID];
    __shared__ float Ls[4][HID];
    __shared__ float qs[4][HID], ks2[4][HID], vs[4][HID];
    __shared__ float sm[4][4];
    __shared__ float am[4][4];

    const int n = threadIdx.x;
    const int task = blockIdx.x;
    const int warp = n >> 5, lane = n & 31;

    #pragma unroll
    for (int i = 0; i < 4; i++)
        Cs[i][n] = g_C[(size_t)(NQ + task*4 + i) * HID + n];
    __syncthreads();

    {
        float x0 = Cs[warp][lane], x1 = Cs[warp][lane+32], x2 = Cs[warp][lane+64], x3 = Cs[warp][lane+96];
        float s = x0+x1+x2+x3;
        #pragma unroll
        for (int o = 16; o; o >>= 1) s += __shfl_xor_sync(0xffffffffu, s, o);
        float mean = s * (1.f/128.f);
        float d0=x0-mean, d1=x1-mean, d2=x2-mean, d3=x3-mean;
        float sq = d0*d0 + d1*d1 + d2*d2 + d3*d3;
        #pragma unroll
        for (int o = 16; o; o >>= 1) sq += __shfl_xor_sync(0xffffffffu, sq, o);
        float inv = rsqrtf(sq * (1.f/128.f) + 1e-5f);
        Ls[warp][lane]    = d0*inv*g1[lane]    + b1[lane];
        Ls[warp][lane+32] = d1*inv*g1[lane+32] + b1[lane+32];
        Ls[warp][lane+64] = d2*inv*g1[lane+64] + b1[lane+64];
        Ls[warp][lane+96] = d3*inv*g1[lane+96] + b1[lane+96];
    }
    __syncthreads();

    {
        float aq[4] = {}, ak[4] = {}, av[4] = {};
        const float* wq = Wq + (size_t)n * HID;
        const float* wk = Wk + (size_t)n * HID;
        const float* wv = Wv + (size_t)n * HID;
        for (int k = 0; k < HID; k++) {
            float q_ = wq[k], k_ = wk[k], v_ = wv[k];
            #pragma unroll
            for (int i = 0; i < 4; i++) {
                float l = Ls[i][k];
                aq[i] += l * q_; ak[i] += l * k_; av[i] += l * v_;
            }
        }
        #pragma unroll
        for (int i = 0; i < 4; i++) {
            qs[i][n]  = aq[i] + bq[n];
            ks2[i][n] = ak[i] + bk[n];
            vs[i][n]  = av[i] + bv[n];
        }
    }
    __syncthreads();

    if (n < 16) {
        int i = n >> 2, j = n & 3;
        float s = 0.f;
        for (int k = 0; k < HID; k++) s += qs[i][k] * ks2[j][k];
        sm[i][j] = s * (1.f / (sqrtf(128.f) + 1e-8f));
    }
    __syncthreads();
    if (n < 4) {
        float r0=sm[n][0], r1=sm[n][1], r2=sm[n][2], r3=sm[n][3];
        float mx = fmaxf(fmaxf(r0, r1), fmaxf(r2, r3));
        float e0=expf(r0-mx), e1=expf(r1-mx), e2=expf(r2-mx), e3=expf(r3-mx);
        float se = e0+e1+e2+e3;
        float a0=e0/se+1e-10f, a1=e1/se+1e-10f, a2=e2/se+1e-10f, a3=e3/se+1e-10f;
        float s2 = a0+a1+a2+a3;
        a0/=s2; a1/=s2; a2/=s2; a3/=s2;
        am[n][0] = fminf(fmaxf(a0, 1e-7f), 1.f);
        am[n][1] = fminf(fmaxf(a1, 1e-7f), 1.f);
        am[n][2] = fminf(fmaxf(a2, 1e-7f), 1.f);
        am[n][3] = fminf(fmaxf(a3, 1e-7f), 1.f);
    }
    __syncthreads();

    #pragma unroll
    for (int i = 0; i < 4; i++)
        Cs[i][n] = am[i][0]*vs[0][n] + am[i][1]*vs[1][n] + am[i][2]*vs[2][n] + am[i][3]*vs[3][n];
    __syncthreads();

    {
        float x0 = Cs[warp][lane], x1 = Cs[warp][lane+32], x2 = Cs[warp][lane+64], x3 = Cs[warp][lane+96];
        float s = x0+x1+x2+x3;
        #pragma unroll
        for (int o = 16; o; o >>= 1) s += __shfl_xor_sync(0xffffffffu, s, o);
        float mean = s * (1.f/128.f);
        float d0=x0-mean, d1=x1-mean, d2=x2-mean, d3=x3-mean;
        float sq = d0*d0 + d1*d1 + d2*d2 + d3*d3;
        #pragma unroll
        for (int o = 16; o; o >>= 1) sq += __shfl_xor_sync(0xffffffffu, sq, o);
        float inv = rsqrtf(sq * (1.f/128.f) + 1e-5f);
        Ls[warp][lane]    = d0*inv*g2[lane]    + b2[lane];
        Ls[warp][lane+32] = d1*inv*g2[lane+32] + b2[lane+32];
        Ls[warp][lane+64] = d2*inv*g2[lane+64] + b2[lane+64];
        Ls[warp][lane+96] = d3*inv*g2[lane+96] + b2[lane+96];
    }
    __syncthreads();

    {
        float ao[4] = {};
        const float* wo = Wo + (size_t)n * HID;
        for (int k = 0; k < HID; k++) {
            float w = wo[k];
            #pragma unroll
            for (int i = 0; i < 4; i++) ao[i] += Ls[i][k] * w;
        }
        #pragma unroll
        for (int i = 0; i < 4; i++) Cs[i][n] = ao[i] + bo[n];
    }
    __syncthreads();

    {
        float x0 = Cs[warp][lane], x1 = Cs[warp][lane+32], x2 = Cs[warp][lane+64], x3 = Cs[warp][lane+96];
        float sq = x0*x0 + x1*x1 + x2*x2 + x3*x3;
        #pragma unroll
        for (int o = 16; o; o >>= 1) sq += __shfl_xor_sync(0xffffffffu, sq, o);
        float inv = 1.f / fmaxf(sqrtf(sq), 1e-8f);
        float* out = g_pn + (size_t)(task*4 + warp) * HID;
        out[lane]    = x0*inv;
        out[lane+32] = x1*inv;
        out[lane+64] = x2*inv;
        out[lane+96] = x3*inv;
    }
}

// =====================================================================
// Kernel 4: logits[t,q,c] = 10 * qn[t,q,:] . pn[t,c,:]
// =====================================================================
__global__ __launch_bounds__(256) void logits_kernel(float* __restrict__ out)
{
    __shared__ float qns[64][132];
    __shared__ float pns[4][HID];
    const int tid = threadIdx.x;
    const int task = blockIdx.x;

    for (int i = tid; i < 512; i += 256)
        pns[i >> 7][i & 127] = g_pn[(size_t)task*512 + i];
    for (int i = tid; i < 2048; i += 256) {
        int r = i >> 5, c4 = (i & 31) << 2;
        *(float4*)&qns[r][c4] = *(const float4*)(g_qn + (size_t)(task*64 + r)*HID + c4);
    }
    __syncthreads();

    int q = tid >> 2, c = tid & 3;
    float s = 0.f;
    #pragma unroll 8
    for (int k = 0; k < HID; k++) s += qns[q][k] * pns[c][k];
    out[(size_t)task*256 + tid] = s * 10.f;
}

// =====================================================================
extern "C" void kernel_launch(void* const* d_in, const int* in_sizes, int n_in,
                              void* d_out, int out_size)
{
    const float* simg = (const float*)d_in[0];
    const float* stxt = (const float*)d_in[1];
    // d_in[2] = support_labels (int64) — unused
    const float* qimg = (const float*)d_in[3];
    const float* qtxt = (const float*)d_in[4];
    const float* Wi = (const float*)d_in[5];  const float* bi = (const float*)d_in[6];
    const float* Wt = (const float*)d_in[7];  const float* bt = (const float*)d_in[8];
    const float* g1 = (const float*)d_in[9];  const float* b1 = (const float*)d_in[10];
    const float* Wq = (const float*)d_in[11]; const float* bq = (const float*)d_in[12];
    const float* Wk = (const float*)d_in[13]; const float* bk = (const float*)d_in[14];
    const float* Wv = (const float*)d_in[15]; const float* bv = (const float*)d_in[16];
    const float* g2 = (const float*)d_in[17]; const float* b2 = (const float*)d_in[18];
    const float* Wo = (const float*)d_in[19]; const float* bo = (const float*)d_in[20];
    float* out = (float*)d_out;

    proj_ffma2_kernel<<<(NTOT / 128) * 2, 256>>>(qimg, qtxt, simg, stxt, Wi, Wt, bi, bt);
    query_kernel<<<512, 256>>>(g1, b1, Wv, bv, g2, b2, Wo, bo);
    support_kernel<<<256, 128>>>(g1, b1, Wq, bq, Wk, bk, Wv, bv, g2, b2, Wo, bo);
    logits_kernel<<<256, 256>>>(out);
}

// round 7
// speedup vs baseline: 1.2969x; 1.1081x over previous
#include <cuda_runtime.h>
#include <math.h>

typedef unsigned long long u64;
typedef unsigned int u32;

#define NQ    16384
#define NSUP  1024
#define NTOT  17408
#define KTOT  2816
#define HID   128

// scratch (static __device__ — no allocations allowed)
__device__ float g_C [NTOT * HID];
__device__ float g_qn[NQ   * HID];
__device__ float g_pn[NSUP * HID];

// ---- packed f32x2 helpers ----
__device__ __forceinline__ u64 fpack(float x, float y) {
    u64 r; asm("mov.b64 %0, {%1, %2};" : "=l"(r) : "f"(x), "f"(y)); return r;
}
__device__ __forceinline__ u64 ffma2(u64 a, u64 b, u64 c) {
    u64 d; asm("fma.rn.f32x2 %0, %1, %2, %3;" : "=l"(d) : "l"(a), "l"(b), "l"(c)); return d;
}
__device__ __forceinline__ float2 funpack(u64 v) {
    float2 f; asm("mov.b64 {%0, %1}, %2;" : "=f"(f.x), "=f"(f.y) : "l"(v)); return f;
}

// round fp32 bits to nearest tf32
__device__ __forceinline__ u32 rtf(float x) { return __float_as_uint(x) + 0x1000u; }

__device__ __forceinline__ void mma_tf32(float c[4], u32 a0, u32 a1, u32 a2, u32 a3,
                                         u32 b0, u32 b1) {
    asm("mma.sync.aligned.m16n8k8.row.col.f32.tf32.tf32.f32 "
        "{%0,%1,%2,%3}, {%4,%5,%6,%7}, {%8,%9}, {%0,%1,%2,%3};"
        : "+f"(c[0]), "+f"(c[1]), "+f"(c[2]), "+f"(c[3])
        : "r"(a0), "r"(a1), "r"(a2), "r"(a3), "r"(b0), "r"(b1));
}

// =====================================================================
// Kernel 1: HYBRID projection GEMM — tensor pipe + fma pipe co-issue
//   warps 0-3: tf32 mma.sync, rows 0-63 of the 128-row tile
//   warps 4-7: scalar FFMA,   rows 64-127
//   grid 136, BK = 32, double-buffered dual-layout smem
// =====================================================================
#define BKH 32
#define NCHH (KTOT / BKH)    // 88
// per-stage float offsets
#define AM_OFF 0             // A_mma  [64][36]
#define BM_OFF 2304          // B_mma  [128][36]
#define AF_OFF 6912          // A_ffma [32][68]  (cols = m-64)
#define BF_OFF 9088          // B_ffma [32][132]
#define STG_F  13312         // floats per stage
#define BIAS_OFF (2 * STG_F) // bias[128]
#define SMEM_H_BYTES ((2 * STG_F + 128) * 4)

__global__ __launch_bounds__(256) void proj_hybrid_kernel(
    const float* __restrict__ qimg, const float* __restrict__ qtxt,
    const float* __restrict__ simg, const float* __restrict__ stxt,
    const float* __restrict__ Wi,   const float* __restrict__ Wt,
    const float* __restrict__ bi,   const float* __restrict__ bt)
{
    extern __shared__ float sm[];
    float* bias_s = sm + BIAS_OFF;

    const int tid  = threadIdx.x;
    const int wid  = tid >> 5;
    const int lane = tid & 31;

    if (tid < HID) bias_s[tid] = bi[tid] + bt[tid];

    // ---- loaders: row = tid/2, 16-float half = (tid&1)*16
    const int lrow = tid >> 1;
    const int lh   = (tid & 1) << 4;
    const float *aimg, *atxt;
    {
        int tok = blockIdx.x * 128 + lrow;
        if (tok < NQ) { aimg = qimg + (size_t)tok * 2048; atxt = qtxt + (size_t)tok * 768; }
        else { int s = tok - NQ; aimg = simg + (size_t)s * 2048; atxt = stxt + (size_t)s * 768; }
    }
    const float* wi_row = Wi + (size_t)lrow * 2048;
    const float* wt_row = Wt + (size_t)lrow * 768;

    // ---- mma mapping (warps 0-3)
    const int g  = lane >> 2;
    const int tq = lane & 3;
    float macc[4][4][4];
    #pragma unroll
    for (int mt = 0; mt < 4; mt++)
        #pragma unroll
        for (int nt = 0; nt < 4; nt++)
            #pragma unroll
            for (int r = 0; r < 4; r++) macc[mt][nt][r] = 0.f;

    // ---- ffma mapping (warps 4-7): t = tid-128; 8M x 8N per thread
    const int ft = tid & 127;
    const int tm = ft >> 4;      // 8 m-groups (rows 64 + tm*8 ..)
    const int tn = ft & 15;      // 16 n-groups (cols tn*8 ..)
    u64 facc[8][4];
    #pragma unroll
    for (int i = 0; i < 8; i++)
        #pragma unroll
        for (int j = 0; j < 4; j++) facc[i][j] = 0ull;

    // prefetch chunk 0 (k0 = 0: img / Wi side)
    float4 ra[4], rb[4];
    #pragma unroll
    for (int j = 0; j < 4; j++) {
        ra[j] = *(const float4*)(aimg + lh + 4 * j);
        rb[j] = *(const float4*)(wi_row + lh + 4 * j);
    }

    for (int c = 0; c < NCHH; c++) {
        float* st = sm + (c & 1) * STG_F;

        // ---- stage current chunk
        if (lrow < 64) {
            // A rows 0-63 -> mma layout, tf32-rounded
            #pragma unroll
            for (int j = 0; j < 4; j++) {
                uint4 v = { rtf(ra[j].x), rtf(ra[j].y), rtf(ra[j].z), rtf(ra[j].w) };
                *(uint4*)&st[AM_OFF + lrow * 36 + lh + 4 * j] = v;
            }
        } else {
            // A rows 64-127 -> ffma layout [k][m], full fp32
            const int m = lrow - 64;
            #pragma unroll
            for (int j = 0; j < 4; j++) {
                st[AF_OFF + (lh + 4*j + 0) * 68 + m] = ra[j].x;
                st[AF_OFF + (lh + 4*j + 1) * 68 + m] = ra[j].y;
                st[AF_OFF + (lh + 4*j + 2) * 68 + m] = ra[j].z;
                st[AF_OFF + (lh + 4*j + 3) * 68 + m] = ra[j].w;
            }
        }
        // B -> both layouts
        #pragma unroll
        for (int j = 0; j < 4; j++) {
            uint4 v = { rtf(rb[j].x), rtf(rb[j].y), rtf(rb[j].z), rtf(rb[j].w) };
            *(uint4*)&st[BM_OFF + lrow * 36 + lh + 4 * j] = v;
            st[BF_OFF + (lh + 4*j + 0) * 132 + lrow] = rb[j].x;
            st[BF_OFF + (lh + 4*j + 1) * 132 + lrow] = rb[j].y;
            st[BF_OFF + (lh + 4*j + 2) * 132 + lrow] = rb[j].z;
            st[BF_OFF + (lh + 4*j + 3) * 132 + lrow] = rb[j].w;
        }
        __syncthreads();

        // ---- prefetch next chunk
        if (c + 1 < NCHH) {
            int k0 = (c + 1) * BKH;
            const float *pa, *pb;
            if (k0 < 2048) { pa = aimg + k0 + lh; pb = wi_row + k0 + lh; }
            else           { pa = atxt + (k0 - 2048) + lh; pb = wt_row + (k0 - 2048) + lh; }
            #pragma unroll
            for (int j = 0; j < 4; j++) { ra[j] = *(const float4*)(pa + 4*j); rb[j] = *(const float4*)(pb + 4*j); }
        }

        // ---- compute
        if (wid < 4) {
            // tensor path: rows 0-63, full N; warp n-window = wid*32
            const u32* Au = (const u32*)(st + AM_OFF);
            const u32* Bu = (const u32*)(st + BM_OFF);
            #pragma unroll
            for (int ks = 0; ks < 4; ks++) {
                const int kc = ks * 8 + tq;
                u32 bf[4][2];
                #pragma unroll
                for (int nt = 0; nt < 4; nt++) {
                    int n = wid * 32 + nt * 8 + g;
                    bf[nt][0] = Bu[n * 36 + kc];
                    bf[nt][1] = Bu[n * 36 + kc + 4];
                }
                #pragma unroll
                for (int mt = 0; mt < 4; mt++) {
                    int r = mt * 16 + g;
                    u32 a0 = Au[r * 36 + kc];
                    u32 a1 = Au[(r + 8) * 36 + kc];
                    u32 a2 = Au[r * 36 + kc + 4];
                    u32 a3 = Au[(r + 8) * 36 + kc + 4];
                    #pragma unroll
                    for (int nt = 0; nt < 4; nt++)
                        mma_tf32(macc[mt][nt], a0, a1, a2, a3, bf[nt][0], bf[nt][1]);
                }
            }
        } else {
            // fma path: rows 64-127
            const float* Af = st + AF_OFF;
            const float* Bf = st + BF_OFF;
            #pragma unroll 8
            for (int k = 0; k < BKH; k++) {
                float4 av0 = *(const float4*)&Af[k * 68 + tm * 8];
                float4 av1 = *(const float4*)&Af[k * 68 + tm * 8 + 4];
                const u64* bp = (const u64*)&Bf[k * 132 + tn * 8];
                u64 bd0 = bp[0], bd1 = bp[1], bd2 = bp[2], bd3 = bp[3];
                u64 ad[8];
                ad[0] = fpack(av0.x, av0.x); ad[1] = fpack(av0.y, av0.y);
                ad[2] = fpack(av0.z, av0.z); ad[3] = fpack(av0.w, av0.w);
                ad[4] = fpack(av1.x, av1.x); ad[5] = fpack(av1.y, av1.y);
                ad[6] = fpack(av1.z, av1.z); ad[7] = fpack(av1.w, av1.w);
                #pragma unroll
                for (int i = 0; i < 8; i++) {
                    facc[i][0] = ffma2(ad[i], bd0, facc[i][0]);
                    facc[i][1] = ffma2(ad[i], bd1, facc[i][1]);
                    facc[i][2] = ffma2(ad[i], bd2, facc[i][2]);
                    facc[i][3] = ffma2(ad[i], bd3, facc[i][3]);
                }
            }
        }
        __syncthreads();
    }

    // ---- epilogue
    const int t0 = blockIdx.x * 128;
    if (wid < 4) {
        #pragma unroll
        for (int mt = 0; mt < 4; mt++) {
            int r = mt * 16 + g;
            #pragma unroll
            for (int nt = 0; nt < 4; nt++) {
                int cc = wid * 32 + nt * 8 + 2 * tq;
                float bx = bias_s[cc], by = bias_s[cc + 1];
                float2 v0 = { macc[mt][nt][0] + bx, macc[mt][nt][1] + by };
                float2 v1 = { macc[mt][nt][2] + bx, macc[mt][nt][3] + by };
                *(float2*)(g_C + (size_t)(t0 + r) * HID + cc)     = v0;
                *(float2*)(g_C + (size_t)(t0 + r + 8) * HID + cc) = v1;
            }
        }
    } else {
        #pragma unroll
        for (int i = 0; i < 8; i++) {
            int row = t0 + 64 + tm * 8 + i;
            float* out = g_C + (size_t)row * HID + tn * 8;
            #pragma unroll
            for (int j = 0; j < 4; j++) {
                float2 v = funpack(facc[i][j]);
                out[2*j]   = v.x + bias_s[tn * 8 + 2*j];
                out[2*j+1] = v.y + bias_s[tn * 8 + 2*j + 1];
            }
        }
    }
}

// =====================================================================
// shared helpers for the 32-token-per-block pipeline kernel
// =====================================================================
__device__ __forceinline__ void ln32(float (*X)[132], const float* __restrict__ g,
                                     const float* __restrict__ b, int warp, int lane)
{
    float4 gg = *(const float4*)(g + lane*4);
    float4 bb = *(const float4*)(b + lane*4);
    #pragma unroll
    for (int it = 0; it < 4; it++) {
        int t = warp*4 + it;
        float4 v = *(const float4*)&X[t][lane*4];
        float s = v.x + v.y + v.z + v.w;
        #pragma unroll
        for (int o = 16; o; o >>= 1) s += __shfl_xor_sync(0xffffffffu, s, o);
        float mean = s * (1.f/128.f);
        float dx = v.x - mean, dy = v.y - mean, dz = v.z - mean, dw = v.w - mean;
        float sq = dx*dx + dy*dy + dz*dz + dw*dw;
        #pragma unroll
        for (int o = 16; o; o >>= 1) sq += __shfl_xor_sync(0xffffffffu, sq, o);
        float inv = rsqrtf(sq * (1.f/128.f) + 1e-5f);
        v.x = dx*inv*gg.x + bb.x;
        v.y = dy*inv*gg.y + bb.y;
        v.z = dz*inv*gg.z + bb.z;
        v.w = dw*inv*gg.w + bb.w;
        *(float4*)&X[t][lane*4] = v;
    }
}

__device__ __forceinline__ void gemm_tile(const float (*X)[132], float (*Ws)[HID],
                                          const float* __restrict__ W,
                                          float acc[4][4], int tid, int tg, int ng)
{
    const int wn = tid >> 1;
    const int wk = (tid & 1) << 3;
    for (int k0 = 0; k0 < HID; k0 += 16) {
        const float* wr = W + (size_t)wn * HID + k0 + wk;
        float4 w0 = *(const float4*)wr;
        float4 w1 = *(const float4*)(wr + 4);
        Ws[wk+0][wn] = w0.x; Ws[wk+1][wn] = w0.y; Ws[wk+2][wn] = w0.z; Ws[wk+3][wn] = w0.w;
        Ws[wk+4][wn] = w1.x; Ws[wk+5][wn] = w1.y; Ws[wk+6][wn] = w1.z; Ws[wk+7][wn] = w1.w;
        __syncthreads();
        #pragma unroll
        for (int kk = 0; kk < 16; kk++) {
            float4 wv = *(const float4*)&Ws[kk][ng << 2];
            #pragma unroll
            for (int i = 0; i < 4; i++) {
                float x = X[tg*4 + i][k0 + kk];
                acc[i][0] += x * wv.x;
                acc[i][1] += x * wv.y;
                acc[i][2] += x * wv.z;
                acc[i][3] += x * wv.w;
            }
        }
        __syncthreads();
    }
}

// =====================================================================
// Kernel 2: query finish
// =====================================================================
__global__ __launch_bounds__(256) void query_kernel(
    const float* __restrict__ g1, const float* __restrict__ b1,
    const float* __restrict__ Wv, const float* __restrict__ bv,
    const float* __restrict__ g2, const float* __restrict__ b2,
    const float* __restrict__ Wo, const float* __restrict__ bo)
{
    __shared__ float Xs[32][132];
    __shared__ float Ys[32][132];
    __shared__ float Ws[16][HID];
    __shared__ float invn[32];

    const int tid = threadIdx.x;
    const int t0  = blockIdx.x * 32;
    const int warp = tid >> 5, lane = tid & 31;
    const int tg = tid >> 5;
    const int ng = tid & 31;

    for (int i = tid; i < 1024; i += 256) {
        int r = i >> 5, c4 = (i & 31) << 2;
        *(float4*)&Xs[r][c4] = *(const float4*)(g_C + (size_t)(t0 + r) * HID + c4);
    }
    __syncthreads();
    ln32(Xs, g1, b1, warp, lane);
    __syncthreads();

    float accv[4][4] = {};
    gemm_tile(Xs, Ws, Wv, accv, tid, tg, ng);
    #pragma unroll
    for (int i = 0; i < 4; i++)
        #pragma unroll
        for (int j = 0; j < 4; j++)
            Ys[tg*4+i][ng*4+j] = accv[i][j] + bv[ng*4+j];
    __syncthreads();
    ln32(Ys, g2, b2, warp, lane);
    __syncthreads();

    float acco[4][4] = {};
    gemm_tile(Ys, Ws, Wo, acco, tid, tg, ng);
    #pragma unroll
    for (int i = 0; i < 4; i++)
        #pragma unroll
        for (int j = 0; j < 4; j++)
            Xs[tg*4+i][ng*4+j] = acco[i][j] + bo[ng*4+j];
    __syncthreads();

    #pragma unroll
    for (int it = 0; it < 4; it++) {
        int t = warp*4 + it;
        float4 v = *(const float4*)&Xs[t][lane*4];
        float sq = v.x*v.x + v.y*v.y + v.z*v.z + v.w*v.w;
        #pragma unroll
        for (int o = 16; o; o >>= 1) sq += __shfl_xor_sync(0xffffffffu, sq, o);
        if (lane == 0) invn[t] = 1.f / fmaxf(sqrtf(sq), 1e-8f);
    }
    __syncthreads();
    #pragma unroll
    for (int i = 0; i < 4; i++) {
        float s = invn[tg*4+i];
        float* out = g_qn + (size_t)(t0 + tg*4 + i) * HID + ng*4;
        #pragma unroll
        for (int j = 0; j < 4; j++) out[j] = Xs[tg*4+i][ng*4+j] * s;
    }
}

// =====================================================================
// Kernel 3: support path
// =====================================================================
__global__ __launch_bounds__(128) void support_kernel(
    const float* __restrict__ g1, const float* __restrict__ b1,
    const float* __restrict__ Wq, const float* __restrict__ bq,
    const float* __restrict__ Wk, const float* __restrict__ bk,
    const float* __restrict__ Wv, const float* __restrict__ bv,
    const float* __restrict__ g2, const float* __restrict__ b2,
    const float* __restrict__ Wo, const float* __restrict__ bo)
{
    __shared__ float Cs[4][HID];
    __shared__ float Ls[4][HID];
    __shared__ float qs[4][HID], ks2[4][HID], vs[4][HID];
    __shared__ float sm[4][4];
    __shared__ float am[4][4];

    const int n = threadIdx.x;
    const int task = blockIdx.x;
    const int warp = n >> 5, lane = n & 31;

    #pragma unroll
    for (int i = 0; i < 4; i++)
        Cs[i][n] = g_C[(size_t)(NQ + task*4 + i) * HID + n];
    __syncthreads();

    {
        float x0 = Cs[warp][lane], x1 = Cs[warp][lane+32], x2 = Cs[warp][lane+64], x3 = Cs[warp][lane+96];
        float s = x0+x1+x2+x3;
        #pragma unroll
        for (int o = 16; o; o >>= 1) s += __shfl_xor_sync(0xffffffffu, s, o);
        float mean = s * (1.f/128.f);
        float d0=x0-mean, d1=x1-mean, d2=x2-mean, d3=x3-mean;
        float sq = d0*d0 + d1*d1 + d2*d2 + d3*d3;
        #pragma unroll
        for (int o = 16; o; o >>= 1) sq += __shfl_xor_sync(0xffffffffu, sq, o);
        float inv = rsqrtf(sq * (1.f/128.f) + 1e-5f);
        Ls[warp][lane]    = d0*inv*g1[lane]    + b1[lane];
        Ls[warp][lane+32] = d1*inv*g1[lane+32] + b1[lane+32];
        Ls[warp][lane+64] = d2*inv*g1[lane+64] + b1[lane+64];
        Ls[warp][lane+96] = d3*inv*g1[lane+96] + b1[lane+96];
    }
    __syncthreads();

    {
        float aq[4] = {}, ak[4] = {}, av[4] = {};
        const float* wq = Wq + (size_t)n * HID;
        const float* wk = Wk + (size_t)n * HID;
        const float* wv = Wv + (size_t)n * HID;
        for (int k = 0; k < HID; k++) {
            float q_ = wq[k], k_ = wk[k], v_ = wv[k];
            #pragma unroll
            for (int i = 0; i < 4; i++) {
                float l = Ls[i][k];
                aq[i] += l * q_; ak[i] += l * k_; av[i] += l * v_;
            }
        }
        #pragma unroll
        for (int i = 0; i < 4; i++) {
            qs[i][n]  = aq[i] + bq[n];
            ks2[i][n] = ak[i] + bk[n];
            vs[i][n]  = av[i] + bv[n];
        }
    }
    __syncthreads();

    if (n < 16) {
        int i = n >> 2, j = n & 3;
        float s = 0.f;
        for (int k = 0; k < HID; k++) s += qs[i][k] * ks2[j][k];
        sm[i][j] = s * (1.f / (sqrtf(128.f) + 1e-8f));
    }
    __syncthreads();
    if (n < 4) {
        float r0=sm[n][0], r1=sm[n][1], r2=sm[n][2], r3=sm[n][3];
        float mx = fmaxf(fmaxf(r0, r1), fmaxf(r2, r3));
        float e0=expf(r0-mx), e1=expf(r1-mx), e2=expf(r2-mx), e3=expf(r3-mx);
        float se = e0+e1+e2+e3;
        float a0=e0/se+1e-10f, a1=e1/se+1e-10f, a2=e2/se+1e-10f, a3=e3/se+1e-10f;
        float s2 = a0+a1+a2+a3;
        a0/=s2; a1/=s2; a2/=s2; a3/=s2;
        am[n][0] = fminf(fmaxf(a0, 1e-7f), 1.f);
        am[n][1] = fminf(fmaxf(a1, 1e-7f), 1.f);
        am[n][2] = fminf(fmaxf(a2, 1e-7f), 1.f);
        am[n][3] = fminf(fmaxf(a3, 1e-7f), 1.f);
    }
    __syncthreads();

    #pragma unroll
    for (int i = 0; i < 4; i++)
        Cs[i][n] = am[i][0]*vs[0][n] + am[i][1]*vs[1][n] + am[i][2]*vs[2][n] + am[i][3]*vs[3][n];
    __syncthreads();

    {
        float x0 = Cs[warp][lane], x1 = Cs[warp][lane+32], x2 = Cs[warp][lane+64], x3 = Cs[warp][lane+96];
        float s = x0+x1+x2+x3;
        #pragma unroll
        for (int o = 16; o; o >>= 1) s += __shfl_xor_sync(0xffffffffu, s, o);
        float mean = s * (1.f/128.f);
        float d0=x0-mean, d1=x1-mean, d2=x2-mean, d3=x3-mean;
        float sq = d0*d0 + d1*d1 + d2*d2 + d3*d3;
        #pragma unroll
        for (int o = 16; o; o >>= 1) sq += __shfl_xor_sync(0xffffffffu, sq, o);
        float inv = rsqrtf(sq * (1.f/128.f) + 1e-5f);
        Ls[warp][lane]    = d0*inv*g2[lane]    + b2[lane];
        Ls[warp][lane+32] = d1*inv*g2[lane+32] + b2[lane+32];
        Ls[warp][lane+64] = d2*inv*g2[lane+64] + b2[lane+64];
        Ls[warp][lane+96] = d3*inv*g2[lane+96] + b2[lane+96];
    }
    __syncthreads();

    {
        float ao[4] = {};
        const float* wo = Wo + (size_t)n * HID;
        for (int k = 0; k < HID; k++) {
            float w = wo[k];
            #pragma unroll
            for (int i = 0; i < 4; i++) ao[i] += Ls[i][k] * w;
        }
        #pragma unroll
        for (int i = 0; i < 4; i++) Cs[i][n] = ao[i] + bo[n];
    }
    __syncthreads();

    {
        float x0 = Cs[warp][lane], x1 = Cs[warp][lane+32], x2 = Cs[warp][lane+64], x3 = Cs[warp][lane+96];
        float sq = x0*x0 + x1*x1 + x2*x2 + x3*x3;
        #pragma unroll
        for (int o = 16; o; o >>= 1) sq += __shfl_xor_sync(0xffffffffu, sq, o);
        float inv = 1.f / fmaxf(sqrtf(sq), 1e-8f);
        float* out = g_pn + (size_t)(task*4 + warp) * HID;
        out[lane]    = x0*inv;
        out[lane+32] = x1*inv;
        out[lane+64] = x2*inv;
        out[lane+96] = x3*inv;
    }
}

// =====================================================================
// Kernel 4: logits
// =====================================================================
__global__ __launch_bounds__(256) void logits_kernel(float* __restrict__ out)
{
    __shared__ float qns[64][132];
    __shared__ float pns[4][HID];
    const int tid = threadIdx.x;
    const int task = blockIdx.x;

    for (int i = tid; i < 512; i += 256)
        pns[i >> 7][i & 127] = g_pn[(size_t)task*512 + i];
    for (int i = tid; i < 2048; i += 256) {
        int r = i >> 5, c4 = (i & 31) << 2;
        *(float4*)&qns[r][c4] = *(const float4*)(g_qn + (size_t)(task*64 + r)*HID + c4);
    }
    __syncthreads();

    int q = tid >> 2, c = tid & 3;
    float s = 0.f;
    #pragma unroll 8
    for (int k = 0; k < HID; k++) s += qns[q][k] * pns[c][k];
    out[(size_t)task*256 + tid] = s * 10.f;
}

// =====================================================================
extern "C" void kernel_launch(void* const* d_in, const int* in_sizes, int n_in,
                              void* d_out, int out_size)
{
    const float* simg = (const float*)d_in[0];
    const float* stxt = (const float*)d_in[1];
    // d_in[2] = support_labels (int64) — unused
    const float* qimg = (const float*)d_in[3];
    const float* qtxt = (const float*)d_in[4];
    const float* Wi = (const float*)d_in[5];  const float* bi = (const float*)d_in[6];
    const float* Wt = (const float*)d_in[7];  const float* bt = (const float*)d_in[8];
    const float* g1 = (const float*)d_in[9];  const float* b1 = (const float*)d_in[10];
    const float* Wq = (const float*)d_in[11]; const float* bq = (const float*)d_in[12];
    const float* Wk = (const float*)d_in[13]; const float* bk = (const float*)d_in[14];
    const float* Wv = (const float*)d_in[15]; const float* bv = (const float*)d_in[16];
    const float* g2 = (const float*)d_in[17]; const float* b2 = (const float*)d_in[18];
    const float* Wo = (const float*)d_in[19]; const float* bo = (const float*)d_in[20];
    float* out = (float*)d_out;

    static int smem_set = 0;
    if (!smem_set) {
        cudaFuncSetAttribute(proj_hybrid_kernel, cudaFuncAttributeMaxDynamicSharedMemorySize, SMEM_H_BYTES);
        smem_set = 1;
    }

    proj_hybrid_kernel<<<NTOT / 128, 256, SMEM_H_BYTES>>>(qimg, qtxt, simg, stxt, Wi, Wt, bi, bt);
    query_kernel<<<512, 256>>>(g1, b1, Wv, bv, g2, b2, Wo, bo);
    support_kernel<<<256, 128>>>(g1, b1, Wq, bq, Wk, bk, Wv, bv, g2, b2, Wo, bo);
    logits_kernel<<<256, 256>>>(out);
}

// round 9
// speedup vs baseline: 1.3302x; 1.0257x over previous
#include <cuda_runtime.h>
#include <math.h>

typedef unsigned long long u64;
typedef unsigned int u32;

#define NQ    16384
#define NSUP  1024
#define NTOT  17408
#define KTOT  2816
#define HID   128

// scratch (static __device__ — no allocations allowed)
__device__ float g_C [NTOT * HID];
__device__ float g_pn[NSUP * HID];

// ---- packed f32x2 helpers ----
__device__ __forceinline__ u64 fpack(float x, float y) {
    u64 r; asm("mov.b64 %0, {%1, %2};" : "=l"(r) : "f"(x), "f"(y)); return r;
}
__device__ __forceinline__ u64 ffma2(u64 a, u64 b, u64 c) {
    u64 d; asm("fma.rn.f32x2 %0, %1, %2, %3;" : "=l"(d) : "l"(a), "l"(b), "l"(c)); return d;
}
__device__ __forceinline__ float2 funpack(u64 v) {
    float2 f; asm("mov.b64 {%0, %1}, %2;" : "=f"(f.x), "=f"(f.y) : "l"(v)); return f;
}

// round fp32 bits to nearest tf32
__device__ __forceinline__ u32 rtf(float x) { return __float_as_uint(x) + 0x1000u; }

__device__ __forceinline__ void mma_tf32(float c[4], u32 a0, u32 a1, u32 a2, u32 a3,
                                         u32 b0, u32 b1) {
    asm("mma.sync.aligned.m16n8k8.row.col.f32.tf32.tf32.f32 "
        "{%0,%1,%2,%3}, {%4,%5,%6,%7}, {%8,%9}, {%0,%1,%2,%3};"
        : "+f"(c[0]), "+f"(c[1]), "+f"(c[2]), "+f"(c[3])
        : "r"(a0), "r"(a1), "r"(a2), "r"(a3), "r"(b0), "r"(b1));
}

// =====================================================================
// Kernel 1: HYBRID projection GEMM (UNCHANGED from R7 — at fma-pipe roofline)
// =====================================================================
#define BKH 32
#define NCHH (KTOT / BKH)    // 88
#define AM_OFF 0             // A_mma  [64][36]
#define BM_OFF 2304          // B_mma  [128][36]
#define AF_OFF 6912          // A_ffma [32][68]
#define BF_OFF 9088          // B_ffma [32][132]
#define STG_F  13312
#define BIAS_OFF (2 * STG_F)
#define SMEM_H_BYTES ((2 * STG_F + 128) * 4)

__global__ __launch_bounds__(256) void proj_hybrid_kernel(
    const float* __restrict__ qimg, const float* __restrict__ qtxt,
    const float* __restrict__ simg, const float* __restrict__ stxt,
    const float* __restrict__ Wi,   const float* __restrict__ Wt,
    const float* __restrict__ bi,   const float* __restrict__ bt)
{
    extern __shared__ float sm[];
    float* bias_s = sm + BIAS_OFF;

    const int tid  = threadIdx.x;
    const int wid  = tid >> 5;
    const int lane = tid & 31;

    if (tid < HID) bias_s[tid] = bi[tid] + bt[tid];

    const int lrow = tid >> 1;
    const int lh   = (tid & 1) << 4;
    const float *aimg, *atxt;
    {
        int tok = blockIdx.x * 128 + lrow;
        if (tok < NQ) { aimg = qimg + (size_t)tok * 2048; atxt = qtxt + (size_t)tok * 768; }
        else { int s = tok - NQ; aimg = simg + (size_t)s * 2048; atxt = stxt + (size_t)s * 768; }
    }
    const float* wi_row = Wi + (size_t)lrow * 2048;
    const float* wt_row = Wt + (size_t)lrow * 768;

    const int g  = lane >> 2;
    const int tq = lane & 3;
    float macc[4][4][4];
    #pragma unroll
    for (int mt = 0; mt < 4; mt++)
        #pragma unroll
        for (int nt = 0; nt < 4; nt++)
            #pragma unroll
            for (int r = 0; r < 4; r++) macc[mt][nt][r] = 0.f;

    const int ft = tid & 127;
    const int tm = ft >> 4;
    const int tn = ft & 15;
    u64 facc[8][4];
    #pragma unroll
    for (int i = 0; i < 8; i++)
        #pragma unroll
        for (int j = 0; j < 4; j++) facc[i][j] = 0ull;

    float4 ra[4], rb[4];
    #pragma unroll
    for (int j = 0; j < 4; j++) {
        ra[j] = *(const float4*)(aimg + lh + 4 * j);
        rb[j] = *(const float4*)(wi_row + lh + 4 * j);
    }

    for (int c = 0; c < NCHH; c++) {
        float* st = sm + (c & 1) * STG_F;

        if (lrow < 64) {
            #pragma unroll
            for (int j = 0; j < 4; j++) {
                uint4 v = { rtf(ra[j].x), rtf(ra[j].y), rtf(ra[j].z), rtf(ra[j].w) };
                *(uint4*)&st[AM_OFF + lrow * 36 + lh + 4 * j] = v;
            }
        } else {
            const int m = lrow - 64;
            #pragma unroll
            for (int j = 0; j < 4; j++) {
                st[AF_OFF + (lh + 4*j + 0) * 68 + m] = ra[j].x;
                st[AF_OFF + (lh + 4*j + 1) * 68 + m] = ra[j].y;
                st[AF_OFF + (lh + 4*j + 2) * 68 + m] = ra[j].z;
                st[AF_OFF + (lh + 4*j + 3) * 68 + m] = ra[j].w;
            }
        }
        #pragma unroll
        for (int j = 0; j < 4; j++) {
            uint4 v = { rtf(rb[j].x), rtf(rb[j].y), rtf(rb[j].z), rtf(rb[j].w) };
            *(uint4*)&st[BM_OFF + lrow * 36 + lh + 4 * j] = v;
            st[BF_OFF + (lh + 4*j + 0) * 132 + lrow] = rb[j].x;
            st[BF_OFF + (lh + 4*j + 1) * 132 + lrow] = rb[j].y;
            st[BF_OFF + (lh + 4*j + 2) * 132 + lrow] = rb[j].z;
            st[BF_OFF + (lh + 4*j + 3) * 132 + lrow] = rb[j].w;
        }
        __syncthreads();

        if (c + 1 < NCHH) {
            int k0 = (c + 1) * BKH;
            const float *pa, *pb;
            if (k0 < 2048) { pa = aimg + k0 + lh; pb = wi_row + k0 + lh; }
            else           { pa = atxt + (k0 - 2048) + lh; pb = wt_row + (k0 - 2048) + lh; }
            #pragma unroll
            for (int j = 0; j < 4; j++) { ra[j] = *(const float4*)(pa + 4*j); rb[j] = *(const float4*)(pb + 4*j); }
        }

        if (wid < 4) {
            const u32* Au = (const u32*)(st + AM_OFF);
            const u32* Bu = (const u32*)(st + BM_OFF);
            #pragma unroll
            for (int ks = 0; ks < 4; ks++) {
                const int kc = ks * 8 + tq;
                u32 bf[4][2];
                #pragma unroll
                for (int nt = 0; nt < 4; nt++) {
                    int n = wid * 32 + nt * 8 + g;
                    bf[nt][0] = Bu[n * 36 + kc];
                    bf[nt][1] = Bu[n * 36 + kc + 4];
                }
                #pragma unroll
                for (int mt = 0; mt < 4; mt++) {
                    int r = mt * 16 + g;
                    u32 a0 = Au[r * 36 + kc];
                    u32 a1 = Au[(r + 8) * 36 + kc];
                    u32 a2 = Au[r * 36 + kc + 4];
                    u32 a3 = Au[(r + 8) * 36 + kc + 4];
                    #pragma unroll
                    for (int nt = 0; nt < 4; nt++)
                        mma_tf32(macc[mt][nt], a0, a1, a2, a3, bf[nt][0], bf[nt][1]);
                }
            }
        } else {
            const float* Af = st + AF_OFF;
            const float* Bf = st + BF_OFF;
            #pragma unroll 8
            for (int k = 0; k < BKH; k++) {
                float4 av0 = *(const float4*)&Af[k * 68 + tm * 8];
                float4 av1 = *(const float4*)&Af[k * 68 + tm * 8 + 4];
                const u64* bp = (const u64*)&Bf[k * 132 + tn * 8];
                u64 bd0 = bp[0], bd1 = bp[1], bd2 = bp[2], bd3 = bp[3];
                u64 ad[8];
                ad[0] = fpack(av0.x, av0.x); ad[1] = fpack(av0.y, av0.y);
                ad[2] = fpack(av0.z, av0.z); ad[3] = fpack(av0.w, av0.w);
                ad[4] = fpack(av1.x, av1.x); ad[5] = fpack(av1.y, av1.y);
                ad[6] = fpack(av1.z, av1.z); ad[7] = fpack(av1.w, av1.w);
                #pragma unroll
                for (int i = 0; i < 8; i++) {
                    facc[i][0] = ffma2(ad[i], bd0, facc[i][0]);
                    facc[i][1] = ffma2(ad[i], bd1, facc[i][1]);
                    facc[i][2] = ffma2(ad[i], bd2, facc[i][2]);
                    facc[i][3] = ffma2(ad[i], bd3, facc[i][3]);
                }
            }
        }
        __syncthreads();
    }

    const int t0 = blockIdx.x * 128;
    if (wid < 4) {
        #pragma unroll
        for (int mt = 0; mt < 4; mt++) {
            int r = mt * 16 + g;
            #pragma unroll
            for (int nt = 0; nt < 4; nt++) {
                int cc = wid * 32 + nt * 8 + 2 * tq;
                float bx = bias_s[cc], by = bias_s[cc + 1];
                float2 v0 = { macc[mt][nt][0] + bx, macc[mt][nt][1] + by };
                float2 v1 = { macc[mt][nt][2] + bx, macc[mt][nt][3] + by };
                *(float2*)(g_C + (size_t)(t0 + r) * HID + cc)     = v0;
                *(float2*)(g_C + (size_t)(t0 + r + 8) * HID + cc) = v1;
            }
        }
    } else {
        #pragma unroll
        for (int i = 0; i < 8; i++) {
            int row = t0 + 64 + tm * 8 + i;
            float* out = g_C + (size_t)row * HID + tn * 8;
            #pragma unroll
            for (int j = 0; j < 4; j++) {
                float2 v = funpack(facc[i][j]);
                out[2*j]   = v.x + bias_s[tn * 8 + 2*j];
                out[2*j+1] = v.y + bias_s[tn * 8 + 2*j + 1];
            }
        }
    }
}

// =====================================================================
// helpers for 32-token pipeline kernel
// =====================================================================
__device__ __forceinline__ void ln32(float (*X)[132], const float* __restrict__ g,
                                     const float* __restrict__ b, int warp, int lane)
{
    float4 gg = *(const float4*)(g + lane*4);
    float4 bb = *(const float4*)(b + lane*4);
    #pragma unroll
    for (int it = 0; it < 4; it++) {
        int t = warp*4 + it;
        float4 v = *(const float4*)&X[t][lane*4];
        float s = v.x + v.y + v.z + v.w;
        #pragma unroll
        for (int o = 16; o; o >>= 1) s += __shfl_xor_sync(0xffffffffu, s, o);
        float mean = s * (1.f/128.f);
        float dx = v.x - mean, dy = v.y - mean, dz = v.z - mean, dw = v.w - mean;
        float sq = dx*dx + dy*dy + dz*dz + dw*dw;
        #pragma unroll
        for (int o = 16; o; o >>= 1) sq += __shfl_xor_sync(0xffffffffu, sq, o);
        float inv = rsqrtf(sq * (1.f/128.f) + 1e-5f);
        v.x = dx*inv*gg.x + bb.x;
        v.y = dy*inv*gg.y + bb.y;
        v.z = dz*inv*gg.z + bb.z;
        v.w = dw*inv*gg.w + bb.w;
        *(float4*)&X[t][lane*4] = v;
    }
}

// 32x128 @ 128x128 GEMM with double-buffered weight staging (1 barrier/chunk)
__device__ __forceinline__ void gemm_tile2(const float (*X)[132], float (*Ws)[16][HID],
                                           const float* __restrict__ W,
                                           float acc[4][4], int tid, int tg, int ng)
{
    const int wn = tid >> 1;
    const int wk = (tid & 1) << 3;

    // preload chunk 0
    {
        const float* wr = W + (size_t)wn * HID + wk;
        float4 w0 = *(const float4*)wr;
        float4 w1 = *(const float4*)(wr + 4);
        Ws[0][wk+0][wn] = w0.x; Ws[0][wk+1][wn] = w0.y; Ws[0][wk+2][wn] = w0.z; Ws[0][wk+3][wn] = w0.w;
        Ws[0][wk+4][wn] = w1.x; Ws[0][wk+5][wn] = w1.y; Ws[0][wk+6][wn] = w1.z; Ws[0][wk+7][wn] = w1.w;
    }
    __syncthreads();

    #pragma unroll
    for (int c = 0; c < 8; c++) {
        const int s = c & 1;
        if (c + 1 < 8) {
            const float* wr = W + (size_t)wn * HID + (c + 1) * 16 + wk;
            float4 w0 = *(const float4*)wr;
            float4 w1 = *(const float4*)(wr + 4);
            float (*Wd)[HID] = Ws[s ^ 1];
            Wd[wk+0][wn] = w0.x; Wd[wk+1][wn] = w0.y; Wd[wk+2][wn] = w0.z; Wd[wk+3][wn] = w0.w;
            Wd[wk+4][wn] = w1.x; Wd[wk+5][wn] = w1.y; Wd[wk+6][wn] = w1.z; Wd[wk+7][wn] = w1.w;
        }
        const int k0 = c * 16;
        #pragma unroll
        for (int kk = 0; kk < 16; kk++) {
            float4 wv = *(const float4*)&Ws[s][kk][ng << 2];
            #pragma unroll
            for (int i = 0; i < 4; i++) {
                float x = X[tg*4 + i][k0 + kk];   // warp-uniform -> smem broadcast
                acc[i][0] += x * wv.x;
                acc[i][1] += x * wv.y;
                acc[i][2] += x * wv.z;
                acc[i][3] += x * wv.w;
            }
        }
        __syncthreads();
    }
}

// =====================================================================
// Kernel 2: FUSED query transform + logits
//   32 tokens per block (half a task). LN1, Wv, LN2, Wo, then
//   logits[q,c] = 10 * invn_q * (X[q,:]·pn[c,:]) written directly.
// =====================================================================
__global__ __launch_bounds__(256) void query_logits_kernel(
    const float* __restrict__ g1, const float* __restrict__ b1,
    const float* __restrict__ Wv, const float* __restrict__ bv,
    const float* __restrict__ g2, const float* __restrict__ b2,
    const float* __restrict__ Wo, const float* __restrict__ bo,
    float* __restrict__ out)
{
    __shared__ float Xs[32][132];
    __shared__ float Ys[32][132];
    __shared__ float Ws[2][16][HID];
    __shared__ float pns[4][HID];
    __shared__ float invn[32];

    const int tid = threadIdx.x;
    const int t0  = blockIdx.x * 32;
    const int task = blockIdx.x >> 1;
    const int warp = tid >> 5, lane = tid & 31;
    const int tg = tid >> 5;
    const int ng = tid & 31;

    // load pn for this task (overlaps with X load)
    for (int i = tid; i < 512; i += 256)
        ((float*)pns)[i] = g_pn[(size_t)task * 512 + i];
    for (int i = tid; i < 1024; i += 256) {
        int r = i >> 5, c4 = (i & 31) << 2;
        *(float4*)&Xs[r][c4] = *(const float4*)(g_C + (size_t)(t0 + r) * HID + c4);
    }
    __syncthreads();
    ln32(Xs, g1, b1, warp, lane);
    __syncthreads();

    float accv[4][4] = {};
    gemm_tile2(Xs, Ws, Wv, accv, tid, tg, ng);
    #pragma unroll
    for (int i = 0; i < 4; i++)
        #pragma unroll
        for (int j = 0; j < 4; j++)
            Ys[tg*4+i][ng*4+j] = accv[i][j] + bv[ng*4+j];
    __syncthreads();
    ln32(Ys, g2, b2, warp, lane);
    __syncthreads();

    float acco[4][4] = {};
    gemm_tile2(Ys, Ws, Wo, acco, tid, tg, ng);
    #pragma unroll
    for (int i = 0; i < 4; i++)
        #pragma unroll
        for (int j = 0; j < 4; j++)
            Xs[tg*4+i][ng*4+j] = acco[i][j] + bo[ng*4+j];
    __syncthreads();

    // row norms
    #pragma unroll
    for (int it = 0; it < 4; it++) {
        int t = warp*4 + it;
        float4 v = *(const float4*)&Xs[t][lane*4];
        float sq = v.x*v.x + v.y*v.y + v.z*v.z + v.w*v.w;
        #pragma unroll
        for (int o = 16; o; o >>= 1) sq += __shfl_xor_sync(0xffffffffu, sq, o);
        if (lane == 0) invn[t] = 1.f / fmaxf(sqrtf(sq), 1e-8f);
    }
    __syncthreads();

    // logits: warp tg owns tokens tg*4..tg*4+3; lane ng owns dims ng*4..+3
    float part[4][4];
    #pragma unroll
    for (int i = 0; i < 4; i++) {
        float4 xv = *(const float4*)&Xs[tg*4 + i][ng*4];
        #pragma unroll
        for (int c = 0; c < 4; c++) {
            float4 pv = *(const float4*)&pns[c][ng*4];
            part[i][c] = xv.x*pv.x + xv.y*pv.y + xv.z*pv.z + xv.w*pv.w;
        }
    }
    #pragma unroll
    for (int i = 0; i < 4; i++)
        #pragma unroll
        for (int c = 0; c < 4; c++)
            #pragma unroll
            for (int o = 16; o; o >>= 1)
                part[i][c] += __shfl_xor_sync(0xffffffffu, part[i][c], o);

    if (lane < 16) {
        int i = lane >> 2, c = lane & 3;
        int q = (blockIdx.x & 1) * 32 + tg * 4 + i;   // q within task
        out[(size_t)task * 256 + q * 4 + c] = part[i][c] * invn[tg*4 + i] * 10.f;
    }
}

// =====================================================================
// Kernel 3: support path — full 4x4 attention per task (runs BEFORE query)
// =====================================================================
__global__ __launch_bounds__(128) void support_kernel(
    const float* __restrict__ g1, const float* __restrict__ b1,
    const float* __restrict__ Wq, const float* __restrict__ bq,
    const float* __restrict__ Wk, const float* __restrict__ bk,
    const float* __restrict__ Wv, const float* __restrict__ bv,
    const float* __restrict__ g2, const float* __restrict__ b2,
    const float* __restrict__ Wo, const float* __restrict__ bo)
{
    __shared__ float Cs[4][HID];
    __shared__ float Ls[4][HID];
    __shared__ float qs[4][HID], ks2[4][HID], vs[4][HID];
    __shared__ float sm[4][4];
    __shared__ float am[4][4];

    const int n = threadIdx.x;
    const int task = blockIdx.x;
    const int warp = n >> 5, lane = n & 31;

    #pragma unroll
    for (int i = 0; i < 4; i++)
        Cs[i][n] = g_C[(size_t)(NQ + task*4 + i) * HID + n];
    __syncthreads();

    {
        float x0 = Cs[warp][lane], x1 = Cs[warp][lane+32], x2 = Cs[warp][lane+64], x3 = Cs[warp][lane+96];
        float s = x0+x1+x2+x3;
        #pragma unroll
        for (int o = 16; o; o >>= 1) s += __shfl_xor_sync(0xffffffffu, s, o);
        float mean = s * (1.f/128.f);
        float d0=x0-mean, d1=x1-mean, d2=x2-mean, d3=x3-mean;
        float sq = d0*d0 + d1*d1 + d2*d2 + d3*d3;
        #pragma unroll
        for (int o = 16; o; o >>= 1) sq += __shfl_xor_sync(0xffffffffu, sq, o);
        float inv = rsqrtf(sq * (1.f/128.f) + 1e-5f);
        Ls[warp][lane]    = d0*inv*g1[lane]    + b1[lane];
        Ls[warp][lane+32] = d1*inv*g1[lane+32] + b1[lane+32];
        Ls[warp][lane+64] = d2*inv*g1[lane+64] + b1[lane+64];
        Ls[warp][lane+96] = d3*inv*g1[lane+96] + b1[lane+96];
    }
    __syncthreads();

    {
        float aq[4] = {}, ak[4] = {}, av[4] = {};
        const float* wq = Wq + (size_t)n * HID;
        const float* wk = Wk + (size_t)n * HID;
        const float* wv = Wv + (size_t)n * HID;
        for (int k = 0; k < HID; k++) {
            float q_ = wq[k], k_ = wk[k], v_ = wv[k];
            #pragma unroll
            for (int i = 0; i < 4; i++) {
                float l = Ls[i][k];
                aq[i] += l * q_; ak[i] += l * k_; av[i] += l * v_;
            }
        }
        #pragma unroll
        for (int i = 0; i < 4; i++) {
            qs[i][n]  = aq[i] + bq[n];
            ks2[i][n] = ak[i] + bk[n];
            vs[i][n]  = av[i] + bv[n];
        }
    }
    __syncthreads();

    if (n < 16) {
        int i = n >> 2, j = n & 3;
        float s = 0.f;
        for (int k = 0; k < HID; k++) s += qs[i][k] * ks2[j][k];
        sm[i][j] = s * (1.f / (sqrtf(128.f) + 1e-8f));
    }
    __syncthreads();
    if (n < 4) {
        float r0=sm[n][0], r1=sm[n][1], r2=sm[n][2], r3=sm[n][3];
        float mx = fmaxf(fmaxf(r0, r1), fmaxf(r2, r3));
        float e0=expf(r0-mx), e1=expf(r1-mx), e2=expf(r2-mx), e3=expf(r3-mx);
        float se = e0+e1+e2+e3;
        float a0=e0/se+1e-10f, a1=e1/se+1e-10f, a2=e2/se+1e-10f, a3=e3/se+1e-10f;
        float s2 = a0+a1+a2+a3;
        a0/=s2; a1/=s2; a2/=s2; a3/=s2;
        am[n][0] = fminf(fmaxf(a0, 1e-7f), 1.f);
        am[n][1] = fminf(fmaxf(a1, 1e-7f), 1.f);
        am[n][2] = fminf(fmaxf(a2, 1e-7f), 1.f);
        am[n][3] = fminf(fmaxf(a3, 1e-7f), 1.f);
    }
    __syncthreads();

    #pragma unroll
    for (int i = 0; i < 4; i++)
        Cs[i][n] = am[i][0]*vs[0][n] + am[i][1]*vs[1][n] + am[i][2]*vs[2][n] + am[i][3]*vs[3][n];
    __syncthreads();

    {
        float x0 = Cs[warp][lane], x1 = Cs[warp][lane+32], x2 = Cs[warp][lane+64], x3 = Cs[warp][lane+96];
        float s = x0+x1+x2+x3;
        #pragma unroll
        for (int o = 16; o; o >>= 1) s += __shfl_xor_sync(0xffffffffu, s, o);
        float mean = s * (1.f/128.f);
        float d0=x0-mean, d1=x1-mean, d2=x2-mean, d3=x3-mean;
        float sq = d0*d0 + d1*d1 + d2*d2 + d3*d3;
        #pragma unroll
        for (int o = 16; o; o >>= 1) sq += __shfl_xor_sync(0xffffffffu, sq, o);
        float inv = rsqrtf(sq * (1.f/128.f) + 1e-5f);
        Ls[warp][lane]    = d0*inv*g2[lane]    + b2[lane];
        Ls[warp][lane+32] = d1*inv*g2[lane+32] + b2[lane+32];
        Ls[warp][lane+64] = d2*inv*g2[lane+64] + b2[lane+64];
        Ls[warp][lane+96] = d3*inv*g2[lane+96] + b2[lane+96];
    }
    __syncthreads();

    {
        float ao[4] = {};
        const float* wo = Wo + (size_t)n * HID;
        for (int k = 0; k < HID; k++) {
            float w = wo[k];
            #pragma unroll
            for (int i = 0; i < 4; i++) ao[i] += Ls[i][k] * w;
        }
        #pragma unroll
        for (int i = 0; i < 4; i++) Cs[i][n] = ao[i] + bo[n];
    }
    __syncthreads();

    {
        float x0 = Cs[warp][lane], x1 = Cs[warp][lane+32], x2 = Cs[warp][lane+64], x3 = Cs[warp][lane+96];
        float sq = x0*x0 + x1*x1 + x2*x2 + x3*x3;
        #pragma unroll
        for (int o = 16; o; o >>= 1) sq += __shfl_xor_sync(0xffffffffu, sq, o);
        float inv = 1.f / fmaxf(sqrtf(sq), 1e-8f);
        float* out = g_pn + (size_t)(task*4 + warp) * HID;
        out[lane]    = x0*inv;
        out[lane+32] = x1*inv;
        out[lane+64] = x2*inv;
        out[lane+96] = x3*inv;
    }
}

// =====================================================================
extern "C" void kernel_launch(void* const* d_in, const int* in_sizes, int n_in,
                              void* d_out, int out_size)
{
    const float* simg = (const float*)d_in[0];
    const float* stxt = (const float*)d_in[1];
    // d_in[2] = support_labels (int64) — unused
    const float* qimg = (const float*)d_in[3];
    const float* qtxt = (const float*)d_in[4];
    const float* Wi = (const float*)d_in[5];  const float* bi = (const float*)d_in[6];
    const float* Wt = (const float*)d_in[7];  const float* bt = (const float*)d_in[8];
    const float* g1 = (const float*)d_in[9];  const float* b1 = (const float*)d_in[10];
    const float* Wq = (const float*)d_in[11]; const float* bq = (const float*)d_in[12];
    const float* Wk = (const float*)d_in[13]; const float* bk = (const float*)d_in[14];
    const float* Wv = (const float*)d_in[15]; const float* bv = (const float*)d_in[16];
    const float* g2 = (const float*)d_in[17]; const float* b2 = (const float*)d_in[18];
    const float* Wo = (const float*)d_in[19]; const float* bo = (const float*)d_in[20];
    float* out = (float*)d_out;

    static int smem_set = 0;
    if (!smem_set) {
        cudaFuncSetAttribute(proj_hybrid_kernel, cudaFuncAttributeMaxDynamicSharedMemorySize, SMEM_H_BYTES);
        smem_set = 1;
    }

    proj_hybrid_kernel<<<NTOT / 128, 256, SMEM_H_BYTES>>>(qimg, qtxt, simg, stxt, Wi, Wt, bi, bt);
    support_kernel<<<256, 128>>>(g1, b1, Wq, bq, Wk, bk, Wv, bv, g2, b2, Wo, bo);
    query_logits_kernel<<<512, 256>>>(g1, b1, Wv, bv, g2, b2, Wo, bo, out);
}